// round 6
// baseline (speedup 1.0000x reference)
#include <cuda_runtime.h>
#include <cstdint>
#include <cstddef>

#define B_ 4096
#define T_ 168
#define D_ 64
#define H_ 128
#define G_ 384   // 3*H

typedef unsigned long long ull;

__device__ __forceinline__ ull ffma2(ull a, ull b, ull c) {
    ull d;
    asm("fma.rn.f32x2 %0, %1, %2, %3;" : "=l"(d) : "l"(a), "l"(b), "l"(c));
    return d;
}
__device__ __forceinline__ float f2sum(ull v) {
    float lo = __uint_as_float((unsigned)(v & 0xffffffffull));
    float hi = __uint_as_float((unsigned)(v >> 32));
    return lo + hi;
}
__device__ __forceinline__ float fast_sigmoid(float x) {
    return __fdividef(1.f, 1.f + __expf(-x));
}
__device__ __forceinline__ float fast_tanh(float x) {
    return __fdividef(2.f, 1.f + __expf(-2.f * x)) - 1.f;
}

__device__ __forceinline__ void cpasync16(void* smem_dst, const void* gsrc) {
    unsigned saddr = (unsigned)__cvta_generic_to_shared(smem_dst);
    asm volatile("cp.async.ca.shared.global [%0], [%1], 16;\n" :: "r"(saddr), "l"(gsrc));
}
#define CP_COMMIT() asm volatile("cp.async.commit_group;\n" ::: "memory")
#define CP_WAIT(n)  asm volatile("cp.async.wait_group %0;\n" :: "n"(n) : "memory")

// Scratch: gx[t][b][g] fp32, ~1.01 GB device global.
__device__ float g_gx[(size_t)T_ * B_ * G_];

// ---------------------------------------------------------------------------
// Kernel A (unchanged, measured 1.10 ms): near its fp32 issue floor for now.
// ---------------------------------------------------------------------------
#define A_NT   96
#define A_MT   128
#define A_PAD  68
#define A_OP   104

__global__ void __launch_bounds__(512, 1)
gx_kernel(const float* __restrict__ feats, const float* __restrict__ W_ih,
          const float* __restrict__ b_ih)
{
    extern __shared__ float smemA[];
    float* sW   = smemA;
    float* sF0  = sW + A_NT * A_PAD;
    float* sF1  = sF0 + A_MT * A_PAD;
    float* sOut = sF1 + A_MT * A_PAD;
    float* sB   = sOut + A_MT * A_OP;

    const int tid  = threadIdx.x;
    const int wid  = tid >> 5;
    const int lane = tid & 31;
    const int rb   = wid >> 2;
    const int gblk = wid & 3;
    const int rg   = lane >> 2;
    const int lg   = lane & 3;
    const int gloc = gblk * 24 + lg * 6;

    const int slice = blockIdx.x & 3;
    const int px    = blockIdx.x >> 2;
    const int g_base = slice * A_NT;

    for (int i = tid; i < A_NT * D_; i += 512) {
        int g = i >> 6, d = i & 63;
        sW[g * A_PAD + d] = W_ih[(size_t)(g_base + g) * (D_ + 1) + d];
    }
    for (int i = tid; i < A_NT; i += 512) sB[i] = b_ih[g_base + i];

    const int NTILES = (B_ * T_) / A_MT;
    float* sF[2] = { sF0, sF1 };

    {
        int t0 = px >> 5, bb0 = (px & 31) * A_MT;
        for (int i = 0; i < 4; i++) {
            int ci = tid + i * 512;
            int row = ci >> 4, seg = ci & 15;
            cpasync16(sF0 + row * A_PAD + seg * 4,
                      feats + ((size_t)(bb0 + row) * T_ + t0) * D_ + seg * 4);
        }
        CP_COMMIT();
    }

    int buf = 0;
    for (int mt = px; mt < NTILES; mt += 37) {
        const int t  = mt >> 5;
        const int bb = (mt & 31) * A_MT;

        int mt_next = mt + 37;
        if (mt_next < NTILES) {
            int tn = mt_next >> 5, bn = (mt_next & 31) * A_MT;
            float* dst = sF[buf ^ 1];
            for (int i = 0; i < 4; i++) {
                int ci = tid + i * 512;
                int row = ci >> 4, seg = ci & 15;
                cpasync16(dst + row * A_PAD + seg * 4,
                          feats + ((size_t)(bn + row) * T_ + tn) * D_ + seg * 4);
            }
            CP_COMMIT();
            CP_WAIT(1);
        } else {
            CP_WAIT(0);
        }
        __syncthreads();

        const ulonglong2* sF16 = reinterpret_cast<const ulonglong2*>(sF[buf]);
        const ulonglong2* sW16 = reinterpret_cast<const ulonglong2*>(sW);

        ull acc[4][6];
        #pragma unroll
        for (int a = 0; a < 4; a++)
            #pragma unroll
            for (int u = 0; u < 6; u++) acc[a][u] = 0ull;

        #pragma unroll 4
        for (int k4 = 0; k4 < 16; k4++) {
            ulonglong2 f[4];
            #pragma unroll
            for (int rr = 0; rr < 4; rr++)
                f[rr] = sF16[(rb * 32 + rg + rr * 8) * 17 + k4];
            #pragma unroll
            for (int u = 0; u < 6; u++) {
                ulonglong2 w = sW16[(gloc + u) * 17 + k4];
                #pragma unroll
                for (int rr = 0; rr < 4; rr++) {
                    acc[rr][u] = ffma2(f[rr].x, w.x, acc[rr][u]);
                    acc[rr][u] = ffma2(f[rr].y, w.y, acc[rr][u]);
                }
            }
        }

        #pragma unroll
        for (int rr = 0; rr < 4; rr++) {
            int row = rb * 32 + rg + rr * 8;
            float* o = &sOut[row * A_OP + gloc];
            #pragma unroll
            for (int v = 0; v < 3; v++) {
                float2 p;
                p.x = f2sum(acc[rr][v * 2 + 0]) + sB[gloc + v * 2 + 0];
                p.y = f2sum(acc[rr][v * 2 + 1]) + sB[gloc + v * 2 + 1];
                *reinterpret_cast<float2*>(o + v * 2) = p;
            }
        }
        __syncthreads();

        for (int i = 0; i < 6; i++) {
            int ci = tid + i * 512;
            int row = ci / 24, seg = ci - row * 24;
            float4 v = *reinterpret_cast<const float4*>(&sOut[row * A_OP + seg * 4]);
            *reinterpret_cast<float4*>(
                &g_gx[((size_t)t * B_ + bb + row) * G_ + g_base + seg * 4]) = v;
        }
        buf ^= 1;
    }
}

// ---------------------------------------------------------------------------
// Kernel B: persistent GRU scan, software-pipelined mainloop.
// 128 blocks x 256 threads (8 warps). Thread tile r=8 rows x 2 channels x
// {r,z,n} = 48 packed accumulators. Mainloop operands (8 h + 6 W ull) are
// explicitly double-buffered in registers: loads for k2+1 issue a half-body
// (~96 issue cycles) before first use, hiding the 29-cyc LDS latency that
// pinned R2/R5 at ~2x the FFMA2 floor (fma pipe was only 52% busy).
// Bank layout (pad 130): h loads 4 addrs spaced 2x4B-banks (conflict-free,
// 8-way bcast); W loads 8 addrs spaced 4 banks (conflict-free, 4-way bcast).
// ---------------------------------------------------------------------------
#define R_    32
#define SWP   130
#define SWP2  65

__global__ void __launch_bounds__(256, 1)
scan_kernel(const float* __restrict__ h0, const float* __restrict__ y0,
            const float* __restrict__ W_ih, const float* __restrict__ W_hh,
            const float* __restrict__ b_hh, const float* __restrict__ Wo,
            const float* __restrict__ bo, float* __restrict__ out)
{
    extern __shared__ float smem[];
    float* sW   = smem;                 // 384*130 floats
    float* sH   = sW + G_ * SWP;        // 32*130
    float* sWy  = sH + R_ * SWP;        // 384
    float* sBhh = sWy + G_;             // 384
    float* sWo  = sBhh + G_;            // 128
    float* sY   = sWo + H_;             // 32
    float* sRed = sY + R_;              // 8*32

    const int tid  = threadIdx.x;
    const int wid  = tid >> 5;          // 0..7
    const int lane = tid & 31;
    const int b0   = blockIdx.x * R_;

    for (int i = tid; i < G_ * H_; i += 256)
        sW[(i >> 7) * SWP + (i & 127)] = W_hh[i];
    for (int i = tid; i < R_ * H_; i += 256)
        sH[(i >> 7) * SWP + (i & 127)] = h0[(size_t)b0 * H_ + i];
    for (int i = tid; i < G_; i += 256) {
        sWy[i]  = W_ih[(size_t)i * (D_ + 1) + D_];
        sBhh[i] = b_hh[i];
    }
    for (int i = tid; i < H_; i += 256) sWo[i] = Wo[i];
    if (tid < R_) sY[tid] = y0[b0 + tid];
    const float bo_v = bo[0];
    __syncthreads();

    const int lg  = lane & 7;             // 0..7 channel-pair group
    const int rg  = lane >> 3;            // 0..3 row group
    const int c0  = wid * 16 + lg * 2;    // channels c0, c0+1

    const ull* sW2 = reinterpret_cast<const ull*>(sW);
    const ull* sH2 = reinterpret_cast<const ull*>(sH);
    const int bR0 = c0 * SWP2;
    const int bR1 = (c0 + 1) * SWP2;
    const int bZ0 = (H_ + c0) * SWP2;
    const int bZ1 = (H_ + c0 + 1) * SWP2;
    const int bN0 = (2 * H_ + c0) * SWP2;
    const int bN1 = (2 * H_ + c0 + 1) * SWP2;

    for (int t = 0; t < T_; t++) {
        const float* gx = g_gx + ((size_t)t * B_ + b0) * G_;

        // gx prefetch: first use in the epilogue, ~14k cycles later
        float2 xr[8], xz[8], xn[8];
        #pragma unroll
        for (int rr = 0; rr < 8; rr++) {
            const float* gxr = gx + (rg + 4 * rr) * G_;
            xr[rr] = *reinterpret_cast<const float2*>(&gxr[c0]);
            xz[rr] = *reinterpret_cast<const float2*>(&gxr[H_ + c0]);
            xn[rr] = *reinterpret_cast<const float2*>(&gxr[2 * H_ + c0]);
        }

        ull ar[8][2], az[8][2], an[8][2];
        #pragma unroll
        for (int rr = 0; rr < 8; rr++)
            #pragma unroll
            for (int jj = 0; jj < 2; jj++) {
                ar[rr][jj] = 0ull; az[rr][jj] = 0ull; an[rr][jj] = 0ull;
            }

        // -------- software-pipelined mainloop: gh = h @ W_hh^T --------
        ull hbA[8], wbA[6], hbB[8], wbB[6];

        auto loadk = [&](ull* hb, ull* wb, int k2) {
            #pragma unroll
            for (int rr = 0; rr < 8; rr++)
                hb[rr] = sH2[(rg + 4 * rr) * SWP2 + k2];
            wb[0] = sW2[bR0 + k2]; wb[1] = sW2[bR1 + k2];
            wb[2] = sW2[bZ0 + k2]; wb[3] = sW2[bZ1 + k2];
            wb[4] = sW2[bN0 + k2]; wb[5] = sW2[bN1 + k2];
        };
        auto fmak = [&](const ull* hb, const ull* wb) {
            #pragma unroll
            for (int rr = 0; rr < 8; rr++) {
                ar[rr][0] = ffma2(hb[rr], wb[0], ar[rr][0]);
                ar[rr][1] = ffma2(hb[rr], wb[1], ar[rr][1]);
                az[rr][0] = ffma2(hb[rr], wb[2], az[rr][0]);
                az[rr][1] = ffma2(hb[rr], wb[3], az[rr][1]);
                an[rr][0] = ffma2(hb[rr], wb[4], an[rr][0]);
                an[rr][1] = ffma2(hb[rr], wb[5], an[rr][1]);
            }
        };

        loadk(hbA, wbA, 0);
        #pragma unroll 1
        for (int k2 = 0; k2 < 62; k2 += 2) {
            loadk(hbB, wbB, k2 + 1);
            fmak(hbA, wbA);
            loadk(hbA, wbA, k2 + 2);
            fmak(hbB, wbB);
        }
        loadk(hbB, wbB, 63);
        fmak(hbA, wbA);
        fmak(hbB, wbB);
        // --------------------------------------------------------------

        // epilogue constants from smem
        const float2 wy_r = *reinterpret_cast<const float2*>(&sWy[c0]);
        const float2 wy_z = *reinterpret_cast<const float2*>(&sWy[H_ + c0]);
        const float2 wy_n = *reinterpret_cast<const float2*>(&sWy[2 * H_ + c0]);
        const float2 bh_r = *reinterpret_cast<const float2*>(&sBhh[c0]);
        const float2 bh_z = *reinterpret_cast<const float2*>(&sBhh[H_ + c0]);
        const float2 bh_n = *reinterpret_cast<const float2*>(&sBhh[2 * H_ + c0]);
        const float2 wo2  = *reinterpret_cast<const float2*>(&sWo[c0]);

        float2 hnew[8];
        float  pacc[8];
        #pragma unroll
        for (int rr = 0; rr < 8; rr++) {
            int row = rg + 4 * rr;
            float y = sY[row];
            float2 hp = *reinterpret_cast<const float2*>(&sH[row * SWP + c0]);

            float r0 = fast_sigmoid(xr[rr].x + y * wy_r.x + bh_r.x + f2sum(ar[rr][0]));
            float z0 = fast_sigmoid(xz[rr].x + y * wy_z.x + bh_z.x + f2sum(az[rr][0]));
            float n0 = fast_tanh  (xn[rr].x + y * wy_n.x + r0 * (bh_n.x + f2sum(an[rr][0])));
            float h0v = (1.f - z0) * n0 + z0 * hp.x;

            float r1 = fast_sigmoid(xr[rr].y + y * wy_r.y + bh_r.y + f2sum(ar[rr][1]));
            float z1 = fast_sigmoid(xz[rr].y + y * wy_z.y + bh_z.y + f2sum(az[rr][1]));
            float n1 = fast_tanh  (xn[rr].y + y * wy_n.y + r1 * (bh_n.y + f2sum(an[rr][1])));
            float h1v = (1.f - z1) * n1 + z1 * hp.y;

            hnew[rr] = make_float2(h0v, h1v);
            pacc[rr] = h0v * wo2.x + h1v * wo2.y;
        }
        __syncthreads();   // all reads of sH for this step done

        #pragma unroll
        for (int rr = 0; rr < 8; rr++) {
            int row = rg + 4 * rr;
            *reinterpret_cast<float2*>(&sH[row * SWP + c0]) = hnew[rr];
        }
        // y reduction: fold 8 lg lanes (same rg) via shfl, then 8 warps
        #pragma unroll
        for (int rr = 0; rr < 8; rr++) {
            pacc[rr] += __shfl_xor_sync(0xffffffffu, pacc[rr], 1);
            pacc[rr] += __shfl_xor_sync(0xffffffffu, pacc[rr], 2);
            pacc[rr] += __shfl_xor_sync(0xffffffffu, pacc[rr], 4);
        }
        if (lg == 0) {
            #pragma unroll
            for (int rr = 0; rr < 8; rr++)
                sRed[wid * R_ + rg + 4 * rr] = pacc[rr];
        }
        __syncthreads();
        if (tid < R_) {
            float s = bo_v;
            #pragma unroll
            for (int w = 0; w < 8; w++) s += sRed[w * R_ + tid];
            sY[tid] = s;
            out[(size_t)(b0 + tid) * T_ + t] = s;
        }
        __syncthreads();
    }
}

// ---------------------------------------------------------------------------
extern "C" void kernel_launch(void* const* d_in, const int* in_sizes, int n_in,
                              void* d_out, int out_size)
{
    const float* feats = (const float*)d_in[0];
    const float* h0    = (const float*)d_in[1];
    const float* y0    = (const float*)d_in[2];
    const float* W_ih  = (const float*)d_in[3];
    const float* W_hh  = (const float*)d_in[4];
    const float* b_ih  = (const float*)d_in[5];
    const float* b_hh  = (const float*)d_in[6];
    const float* Wo    = (const float*)d_in[7];
    const float* bo    = (const float*)d_in[8];
    float* out = (float*)d_out;

    const int smemA = (A_NT * A_PAD + 2 * A_MT * A_PAD + A_MT * A_OP + A_NT)
                      * (int)sizeof(float);
    cudaFuncSetAttribute(gx_kernel, cudaFuncAttributeMaxDynamicSharedMemorySize, smemA);
    gx_kernel<<<148, 512, smemA>>>(feats, W_ih, b_ih);

    const int smemB = (G_ * SWP + R_ * SWP + G_ + G_ + H_ + R_ + 8 * R_)
                      * (int)sizeof(float);
    cudaFuncSetAttribute(scan_kernel, cudaFuncAttributeMaxDynamicSharedMemorySize, smemB);
    scan_kernel<<<B_ / R_, 256, smemB>>>(h0, y0, W_ih, W_hh, b_hh, Wo, bo, out);
}

// round 11
// speedup vs baseline: 1.3858x; 1.3858x over previous
#include <cuda_runtime.h>
#include <cuda_bf16.h>
#include <cstdint>
#include <cstddef>

#define B_ 4096
#define T_ 168
#define D_ 64
#define H_ 128
#define G_ 384   // 3*H

typedef unsigned long long ull;

// ---------------------------------------------------------------------------
// helpers
// ---------------------------------------------------------------------------
__device__ __forceinline__ ull ffma2(ull a, ull b, ull c) {
    ull d;
    asm("fma.rn.f32x2 %0, %1, %2, %3;" : "=l"(d) : "l"(a), "l"(b), "l"(c));
    return d;
}
__device__ __forceinline__ float f2sum(ull v) {
    float lo = __uint_as_float((unsigned)(v & 0xffffffffull));
    float hi = __uint_as_float((unsigned)(v >> 32));
    return lo + hi;
}
__device__ __forceinline__ float fast_sigmoid(float x) {
    return __fdividef(1.f, 1.f + __expf(-x));
}
__device__ __forceinline__ float fast_tanh(float x) {
    return __fdividef(2.f, 1.f + __expf(-2.f * x)) - 1.f;
}
__device__ __forceinline__ void cpasync16(void* smem_dst, const void* gsrc) {
    unsigned saddr = (unsigned)__cvta_generic_to_shared(smem_dst);
    asm volatile("cp.async.ca.shared.global [%0], [%1], 16;\n" :: "r"(saddr), "l"(gsrc));
}
#define CP_COMMIT() asm volatile("cp.async.commit_group;\n" ::: "memory")
#define CP_WAIT(n)  asm volatile("cp.async.wait_group %0;\n" :: "n"(n) : "memory")

// warp-level bf16 tensor-core mma (HMMA path, plain sm_100-legal PTX)
#define MMA_BF16(c, a, b) \
    asm volatile("mma.sync.aligned.m16n8k16.row.col.f32.bf16.bf16.f32 " \
        "{%0,%1,%2,%3}, {%4,%5,%6,%7}, {%8,%9}, {%0,%1,%2,%3};" \
        : "+f"((c)[0]), "+f"((c)[1]), "+f"((c)[2]), "+f"((c)[3]) \
        : "r"((a)[0]), "r"((a)[1]), "r"((a)[2]), "r"((a)[3]), \
          "r"((b).x), "r"((b).y))

// Scratch: gx[t][b][g] fp32, ~1.01 GB device global.
__device__ float g_gx[(size_t)T_ * B_ * G_];

// ---------------------------------------------------------------------------
// Kernel A (R5-measured SIMT version, 1.10 ms): unchanged.
// ---------------------------------------------------------------------------
#define A_NT   96
#define A_MT   128
#define A_PAD  68
#define A_OP   104

__global__ void __launch_bounds__(512, 1)
gx_kernel(const float* __restrict__ feats, const float* __restrict__ W_ih,
          const float* __restrict__ b_ih)
{
    extern __shared__ float smemA[];
    float* sW   = smemA;
    float* sF0  = sW + A_NT * A_PAD;
    float* sF1  = sF0 + A_MT * A_PAD;
    float* sOut = sF1 + A_MT * A_PAD;
    float* sB   = sOut + A_MT * A_OP;

    const int tid  = threadIdx.x;
    const int wid  = tid >> 5;
    const int lane = tid & 31;
    const int rb   = wid >> 2;
    const int gblk = wid & 3;
    const int rg   = lane >> 2;
    const int lg   = lane & 3;
    const int gloc = gblk * 24 + lg * 6;

    const int slice = blockIdx.x & 3;
    const int px    = blockIdx.x >> 2;
    const int g_base = slice * A_NT;

    for (int i = tid; i < A_NT * D_; i += 512) {
        int g = i >> 6, d = i & 63;
        sW[g * A_PAD + d] = W_ih[(size_t)(g_base + g) * (D_ + 1) + d];
    }
    for (int i = tid; i < A_NT; i += 512) sB[i] = b_ih[g_base + i];

    const int NTILES = (B_ * T_) / A_MT;
    float* sF[2] = { sF0, sF1 };

    {
        int t0 = px >> 5, bb0 = (px & 31) * A_MT;
        for (int i = 0; i < 4; i++) {
            int ci = tid + i * 512;
            int row = ci >> 4, seg = ci & 15;
            cpasync16(sF0 + row * A_PAD + seg * 4,
                      feats + ((size_t)(bb0 + row) * T_ + t0) * D_ + seg * 4);
        }
        CP_COMMIT();
    }

    int buf = 0;
    for (int mt = px; mt < NTILES; mt += 37) {
        const int t  = mt >> 5;
        const int bb = (mt & 31) * A_MT;

        int mt_next = mt + 37;
        if (mt_next < NTILES) {
            int tn = mt_next >> 5, bn = (mt_next & 31) * A_MT;
            float* dst = sF[buf ^ 1];
            for (int i = 0; i < 4; i++) {
                int ci = tid + i * 512;
                int row = ci >> 4, seg = ci & 15;
                cpasync16(dst + row * A_PAD + seg * 4,
                          feats + ((size_t)(bn + row) * T_ + tn) * D_ + seg * 4);
            }
            CP_COMMIT();
            CP_WAIT(1);
        } else {
            CP_WAIT(0);
        }
        __syncthreads();

        const ulonglong2* sF16 = reinterpret_cast<const ulonglong2*>(sF[buf]);
        const ulonglong2* sW16 = reinterpret_cast<const ulonglong2*>(sW);

        ull acc[4][6];
        #pragma unroll
        for (int a = 0; a < 4; a++)
            #pragma unroll
            for (int u = 0; u < 6; u++) acc[a][u] = 0ull;

        #pragma unroll 4
        for (int k4 = 0; k4 < 16; k4++) {
            ulonglong2 f[4];
            #pragma unroll
            for (int rr = 0; rr < 4; rr++)
                f[rr] = sF16[(rb * 32 + rg + rr * 8) * 17 + k4];
            #pragma unroll
            for (int u = 0; u < 6; u++) {
                ulonglong2 w = sW16[(gloc + u) * 17 + k4];
                #pragma unroll
                for (int rr = 0; rr < 4; rr++) {
                    acc[rr][u] = ffma2(f[rr].x, w.x, acc[rr][u]);
                    acc[rr][u] = ffma2(f[rr].y, w.y, acc[rr][u]);
                }
            }
        }

        #pragma unroll
        for (int rr = 0; rr < 4; rr++) {
            int row = rb * 32 + rg + rr * 8;
            float* o = &sOut[row * A_OP + gloc];
            #pragma unroll
            for (int v = 0; v < 3; v++) {
                float2 p;
                p.x = f2sum(acc[rr][v * 2 + 0]) + sB[gloc + v * 2 + 0];
                p.y = f2sum(acc[rr][v * 2 + 1]) + sB[gloc + v * 2 + 1];
                *reinterpret_cast<float2*>(o + v * 2) = p;
            }
        }
        __syncthreads();

        for (int i = 0; i < 6; i++) {
            int ci = tid + i * 512;
            int row = ci / 24, seg = ci - row * 24;
            float4 v = *reinterpret_cast<const float4*>(&sOut[row * A_OP + seg * 4]);
            *reinterpret_cast<float4*>(
                &g_gx[((size_t)t * B_ + bb + row) * G_ + g_base + seg * 4]) = v;
        }
        buf ^= 1;
    }
}

// ---------------------------------------------------------------------------
// Kernel B: GRU scan with warp-level bf16 tensor-core mma (mma.sync/HMMA).
// 128 blocks x 256 threads (8 warps), 32 batch rows each.
// gh = h @ W_hh^T done as 4-product bf16 split (hi/lo on both operands,
// fp32 accum): residual error ~2^-17 per element.
// W_hh split once at init into PRE-ARRANGED B-fragment order in smem
// (no ldmatrix; frag mapping is by construction). h kept as bf16 hi/lo
// images [32 x 288B padded] -> conflict-free A-frag LDS.
// Warp w owns gate cols {reg*128 + w*16 .. +15} for reg in {r,z,n} ->
// r/z/n fragments align thread-locally for the gate math.
// ---------------------------------------------------------------------------
#define SB_HI  0          // W_hh hi fragments (98304 B)
#define SB_LO  98304      // W_hh lo fragments (98304 B)
#define SH_HI  196608     // h hi image, 32 rows x 288 B
#define SH_LO  205824     // h lo image
#define SWY    215040     // wy fp32 [384]
#define SBH    216576     // b_hh fp32 [384]
#define SWO    218112     // Wo fp32 [128]
#define SY     218624     // y fp32 [32]
#define SRED   218752     // 8 x 32 fp32
#define S_TOT  219776

__global__ void __launch_bounds__(256, 1)
scan_kernel(const float* __restrict__ h0, const float* __restrict__ y0,
            const float* __restrict__ W_ih, const float* __restrict__ W_hh,
            const float* __restrict__ b_hh, const float* __restrict__ Wo,
            const float* __restrict__ bo, float* __restrict__ out)
{
    extern __shared__ char smemS[];
    const int tid  = threadIdx.x;
    const int w    = tid >> 5;          // warp 0..7
    const int lane = tid & 31;
    const int g    = lane >> 2;         // 0..7
    const int tg   = lane & 3;          // 0..3
    const int b0   = blockIdx.x * 32;

    float* sWyf = (float*)(smemS + SWY);
    float* sBhf = (float*)(smemS + SBH);
    float* sWof = (float*)(smemS + SWO);
    float* sYf  = (float*)(smemS + SY);
    float* sRf  = (float*)(smemS + SRED);

    // ---- init: W_hh -> bf16 hi/lo fragments in exact mma B-frag order ----
    for (int idx = tid; idx < G_ * H_; idx += 256) {
        int n = idx >> 7;               // gate col 0..383
        int k = idx & 127;
        float wv = W_hh[idx];
        __nv_bfloat16 h16 = __float2bfloat16(wv);
        float lof = wv - __bfloat162float(h16);
        __nv_bfloat16 l16 = __float2bfloat16(lof);
        int region = n >> 7, off = n & 127;
        int ww = off >> 4, nt = (off >> 3) & 1, n8 = off & 7;
        int kstep = k >> 4, kk = k & 15;
        int reg  = kk >> 3;
        int tgi  = (kk & 7) >> 1;
        int half = kk & 1;
        int ln   = n8 * 4 + tgi;
        int fidx = ((ww * 3 + region) * 2 + nt) * 8 + kstep;
        int boff = fidx * 256 + ln * 8 + reg * 4 + half * 2;
        *(unsigned short*)(smemS + SB_HI + boff) = __bfloat16_as_ushort(h16);
        *(unsigned short*)(smemS + SB_LO + boff) = __bfloat16_as_ushort(l16);
    }
    // h0 -> hi/lo images
    for (int i = tid; i < 32 * H_; i += 256) {
        int row = i >> 7, k = i & 127;
        float hv = h0[(size_t)b0 * H_ + i];
        __nv_bfloat16 h16 = __float2bfloat16(hv);
        float lof = hv - __bfloat162float(h16);
        *(unsigned short*)(smemS + SH_HI + row * 288 + k * 2) = __bfloat16_as_ushort(h16);
        *(unsigned short*)(smemS + SH_LO + row * 288 + k * 2) =
            __bfloat16_as_ushort(__float2bfloat16(lof));
    }
    for (int i = tid; i < G_; i += 256) {
        sWyf[i] = W_ih[(size_t)i * (D_ + 1) + D_];
        sBhf[i] = b_hh[i];
    }
    for (int i = tid; i < H_; i += 256) sWof[i] = Wo[i];
    if (tid < 32) sYf[tid] = y0[b0 + tid];
    const float bo_v = bo[0];
    __syncthreads();

    const int colb0 = w * 16 + 2 * tg;   // nt adds +8

    for (int t = 0; t < T_; t++) {
        const float* gx = g_gx + ((size_t)t * B_ + b0) * G_;

        // gx prefetch (consumed in epilogue): [region][mt][rr][nt]
        float2 xg[3][2][2][2];
        #pragma unroll
        for (int region = 0; region < 3; region++)
            #pragma unroll
            for (int mt = 0; mt < 2; mt++)
                #pragma unroll
                for (int rr = 0; rr < 2; rr++)
                    #pragma unroll
                    for (int nt = 0; nt < 2; nt++) {
                        int row = mt * 16 + rr * 8 + g;
                        xg[region][mt][rr][nt] = *(const float2*)(
                            gx + (size_t)row * G_ + region * 128 + colb0 + nt * 8);
                    }

        // accumulators: [mtile][region][ntile][c0..c3]
        float c[2][3][2][4];
        #pragma unroll
        for (int mt = 0; mt < 2; mt++)
            #pragma unroll
            for (int region = 0; region < 3; region++)
                #pragma unroll
                for (int nt = 0; nt < 2; nt++)
                    #pragma unroll
                    for (int q = 0; q < 4; q++) c[mt][region][nt][q] = 0.f;

        // ------ tensor-core mainloop ------
        #pragma unroll 2
        for (int ks = 0; ks < 8; ks++) {
            uint32_t ahi[2][4], alo[2][4];
            #pragma unroll
            for (int mt = 0; mt < 2; mt++) {
                const char* ph = smemS + SH_HI + (mt * 16 + g) * 288 + ks * 32 + tg * 4;
                ahi[mt][0] = *(const uint32_t*)(ph);
                ahi[mt][1] = *(const uint32_t*)(ph + 8 * 288);
                ahi[mt][2] = *(const uint32_t*)(ph + 16);
                ahi[mt][3] = *(const uint32_t*)(ph + 8 * 288 + 16);
                const char* pl = smemS + SH_LO + (mt * 16 + g) * 288 + ks * 32 + tg * 4;
                alo[mt][0] = *(const uint32_t*)(pl);
                alo[mt][1] = *(const uint32_t*)(pl + 8 * 288);
                alo[mt][2] = *(const uint32_t*)(pl + 16);
                alo[mt][3] = *(const uint32_t*)(pl + 8 * 288 + 16);
            }
            #pragma unroll
            for (int region = 0; region < 3; region++)
                #pragma unroll
                for (int nt = 0; nt < 2; nt++) {
                    int fb = (((w * 3 + region) * 2 + nt) * 8 + ks) * 256 + lane * 8;
                    uint2 bhi = *(const uint2*)(smemS + SB_HI + fb);
                    uint2 blo = *(const uint2*)(smemS + SB_LO + fb);
                    #pragma unroll
                    for (int mt = 0; mt < 2; mt++) {
                        MMA_BF16(c[mt][region][nt], ahi[mt], bhi);
                        MMA_BF16(c[mt][region][nt], ahi[mt], blo);
                        MMA_BF16(c[mt][region][nt], alo[mt], bhi);
                        MMA_BF16(c[mt][region][nt], alo[mt], blo);
                    }
                }
        }

        // ------ epilogue: gates + h update ------
        float2 wyc[3][2], bhc[3][2], woc[2];
        #pragma unroll
        for (int region = 0; region < 3; region++)
            #pragma unroll
            for (int nt = 0; nt < 2; nt++) {
                wyc[region][nt] = *(const float2*)(sWyf + region * 128 + colb0 + nt * 8);
                bhc[region][nt] = *(const float2*)(sBhf + region * 128 + colb0 + nt * 8);
            }
        woc[0] = *(const float2*)(sWof + colb0);
        woc[1] = *(const float2*)(sWof + colb0 + 8);

        float pacc[4] = {0.f, 0.f, 0.f, 0.f};
        uint32_t hhiN[2][2][2], hloN[2][2][2];
        #pragma unroll
        for (int mt = 0; mt < 2; mt++)
            #pragma unroll
            for (int rr = 0; rr < 2; rr++) {
                int row = mt * 16 + rr * 8 + g;
                float y = sYf[row];
                #pragma unroll
                for (int nt = 0; nt < 2; nt++) {
                    int cb = (colb0 + nt * 8) * 2;
                    uint32_t hpw = *(const uint32_t*)(smemS + SH_HI + row * 288 + cb);
                    uint32_t lpw = *(const uint32_t*)(smemS + SH_LO + row * 288 + cb);
                    float hp0 = __bfloat162float(__ushort_as_bfloat16((unsigned short)(hpw)))
                              + __bfloat162float(__ushort_as_bfloat16((unsigned short)(lpw)));
                    float hp1 = __bfloat162float(__ushort_as_bfloat16((unsigned short)(hpw >> 16)))
                              + __bfloat162float(__ushort_as_bfloat16((unsigned short)(lpw >> 16)));

                    int i0 = rr * 2;
                    float r0 = fast_sigmoid(xg[0][mt][rr][nt].x + y * wyc[0][nt].x + bhc[0][nt].x + c[mt][0][nt][i0]);
                    float z0 = fast_sigmoid(xg[1][mt][rr][nt].x + y * wyc[1][nt].x + bhc[1][nt].x + c[mt][1][nt][i0]);
                    float n0 = fast_tanh  (xg[2][mt][rr][nt].x + y * wyc[2][nt].x + r0 * (bhc[2][nt].x + c[mt][2][nt][i0]));
                    float h0v = (1.f - z0) * n0 + z0 * hp0;

                    float r1 = fast_sigmoid(xg[0][mt][rr][nt].y + y * wyc[0][nt].y + bhc[0][nt].y + c[mt][0][nt][i0 + 1]);
                    float z1 = fast_sigmoid(xg[1][mt][rr][nt].y + y * wyc[1][nt].y + bhc[1][nt].y + c[mt][1][nt][i0 + 1]);
                    float n1 = fast_tanh  (xg[2][mt][rr][nt].y + y * wyc[2][nt].y + r1 * (bhc[2][nt].y + c[mt][2][nt][i0 + 1]));
                    float h1v = (1.f - z1) * n1 + z1 * hp1;

                    pacc[mt * 2 + rr] += h0v * woc[nt].x + h1v * woc[nt].y;

                    __nv_bfloat16 hb0 = __float2bfloat16(h0v);
                    __nv_bfloat16 hb1 = __float2bfloat16(h1v);
                    float l0 = h0v - __bfloat162float(hb0);
                    float l1 = h1v - __bfloat162float(hb1);
                    __nv_bfloat16 lb0 = __float2bfloat16(l0);
                    __nv_bfloat16 lb1 = __float2bfloat16(l1);
                    hhiN[mt][rr][nt] = (uint32_t)__bfloat16_as_ushort(hb0)
                                     | ((uint32_t)__bfloat16_as_ushort(hb1) << 16);
                    hloN[mt][rr][nt] = (uint32_t)__bfloat16_as_ushort(lb0)
                                     | ((uint32_t)__bfloat16_as_ushort(lb1) << 16);
                }
            }
        __syncthreads();   // all reads of sH done block-wide

        #pragma unroll
        for (int mt = 0; mt < 2; mt++)
            #pragma unroll
            for (int rr = 0; rr < 2; rr++) {
                int row = mt * 16 + rr * 8 + g;
                #pragma unroll
                for (int nt = 0; nt < 2; nt++) {
                    int cb = (colb0 + nt * 8) * 2;
                    *(uint32_t*)(smemS + SH_HI + row * 288 + cb) = hhiN[mt][rr][nt];
                    *(uint32_t*)(smemS + SH_LO + row * 288 + cb) = hloN[mt][rr][nt];
                }
            }

        // y reduction: fold tg lanes, then warps
        #pragma unroll
        for (int i = 0; i < 4; i++) {
            pacc[i] += __shfl_xor_sync(0xffffffffu, pacc[i], 1);
            pacc[i] += __shfl_xor_sync(0xffffffffu, pacc[i], 2);
        }
        if (tg == 0) {
            sRf[w * 32 + g]      = pacc[0];
            sRf[w * 32 + g + 8]  = pacc[1];
            sRf[w * 32 + g + 16] = pacc[2];
            sRf[w * 32 + g + 24] = pacc[3];
        }
        __syncthreads();
        if (tid < 32) {
            float s = bo_v;
            #pragma unroll
            for (int ww = 0; ww < 8; ww++) s += sRf[ww * 32 + tid];
            sYf[tid] = s;
            out[(size_t)(b0 + tid) * T_ + t] = s;
        }
        __syncthreads();
    }
}

// ---------------------------------------------------------------------------
extern "C" void kernel_launch(void* const* d_in, const int* in_sizes, int n_in,
                              void* d_out, int out_size)
{
    const float* feats = (const float*)d_in[0];
    const float* h0    = (const float*)d_in[1];
    const float* y0    = (const float*)d_in[2];
    const float* W_ih  = (const float*)d_in[3];
    const float* W_hh  = (const float*)d_in[4];
    const float* b_ih  = (const float*)d_in[5];
    const float* b_hh  = (const float*)d_in[6];
    const float* Wo    = (const float*)d_in[7];
    const float* bo    = (const float*)d_in[8];
    float* out = (float*)d_out;

    const int smemA = (A_NT * A_PAD + 2 * A_MT * A_PAD + A_MT * A_OP + A_NT)
                      * (int)sizeof(float);
    cudaFuncSetAttribute(gx_kernel, cudaFuncAttributeMaxDynamicSharedMemorySize, smemA);
    gx_kernel<<<148, 512, smemA>>>(feats, W_ih, b_ih);

    cudaFuncSetAttribute(scan_kernel, cudaFuncAttributeMaxDynamicSharedMemorySize, S_TOT);
    scan_kernel<<<B_ / 32, 256, S_TOT>>>(h0, y0, W_ih, W_hh, b_hh, Wo, bo, out);
}

// round 12
// speedup vs baseline: 1.9499x; 1.4071x over previous
#include <cuda_runtime.h>
#include <cuda_bf16.h>
#include <cstdint>
#include <cstddef>

#define B_ 4096
#define T_ 168
#define D_ 64
#define H_ 128
#define G_ 384   // 3*H

typedef unsigned long long ull;

// ---------------------------------------------------------------------------
// helpers
// ---------------------------------------------------------------------------
__device__ __forceinline__ float fast_sigmoid(float x) {
    return __fdividef(1.f, 1.f + __expf(-x));
}
__device__ __forceinline__ float fast_tanh(float x) {
    return __fdividef(2.f, 1.f + __expf(-2.f * x)) - 1.f;
}

// warp-level bf16 tensor-core mma (HMMA path, plain sm_100-legal PTX)
#define MMA_BF16(c, a, b) \
    asm volatile("mma.sync.aligned.m16n8k16.row.col.f32.bf16.bf16.f32 " \
        "{%0,%1,%2,%3}, {%4,%5,%6,%7}, {%8,%9}, {%0,%1,%2,%3};" \
        : "+f"((c)[0]), "+f"((c)[1]), "+f"((c)[2]), "+f"((c)[3]) \
        : "r"((a)[0]), "r"((a)[1]), "r"((a)[2]), "r"((a)[3]), \
          "r"((b).x), "r"((b).y))

// Scratch: gx[t][b][g] fp32, ~1.01 GB device global.
__device__ float g_gx[(size_t)T_ * B_ * G_];

// ---------------------------------------------------------------------------
// Kernel A: gx = feats . W_ih[:, :64]^T + b_ih via mma.sync bf16,
// 3-product split (hi*hi + hi*lo + lo*hi; lo*lo ~2^-16 rel, dropped —
// feed-forward error, does not compound through the recurrence).
// 148 persistent blocks x 256 threads (8 warps). Per 128-row tile:
// feats prefetched into registers one tile ahead (LDG hides under MMA),
// converted to bf16 hi/lo smem images; W_ih pre-packed once into exact
// B-fragment order (same validated layout as the scan, 4 k-steps).
// Output: accumulators + bias stored directly, float2 per lane-group =
// full 32B sectors.
// ---------------------------------------------------------------------------
#define GB_HI  0                      // W_ih hi fragments (49152 B)
#define GB_LO  49152                  // W_ih lo fragments (49152 B)
#define GA_HI  98304                  // feats hi image 128 x 136 B
#define GA_LO  (98304 + 17408)
#define GBIAS  (98304 + 34816)        // 384 f32
#define G_TOT  (GBIAS + 1536)

__global__ void __launch_bounds__(256, 1)
gx_kernel(const float* __restrict__ feats, const float* __restrict__ W_ih,
          const float* __restrict__ b_ih)
{
    extern __shared__ char smemA[];
    const int tid  = threadIdx.x;
    const int w    = tid >> 5;
    const int lane = tid & 31;
    const int g    = lane >> 2;
    const int tg   = lane & 3;

    float* sBias = (float*)(smemA + GBIAS);

    // ---- init: W_ih[:, :64] -> bf16 hi/lo B-fragments (once) ----
    for (int idx = tid; idx < G_ * D_; idx += 256) {
        int n = idx >> 6;               // gate col 0..383
        int k = idx & 63;
        float wv = W_ih[(size_t)n * (D_ + 1) + k];
        __nv_bfloat16 h16 = __float2bfloat16(wv);
        float lof = wv - __bfloat162float(h16);
        __nv_bfloat16 l16 = __float2bfloat16(lof);
        int region = n >> 7, off = n & 127;
        int ww = off >> 4, nt = (off >> 3) & 1, n8 = off & 7;
        int kstep = k >> 4, kk = k & 15;
        int reg  = kk >> 3;
        int tgi  = (kk & 7) >> 1;
        int half = kk & 1;
        int ln   = n8 * 4 + tgi;
        int fidx = ((ww * 3 + region) * 2 + nt) * 4 + kstep;
        int boff = fidx * 256 + ln * 8 + reg * 4 + half * 2;
        *(unsigned short*)(smemA + GB_HI + boff) = __bfloat16_as_ushort(h16);
        *(unsigned short*)(smemA + GB_LO + boff) = __bfloat16_as_ushort(l16);
    }
    for (int i = tid; i < G_; i += 256) sBias[i] = b_ih[i];
    __syncthreads();

    const int NTILES = (B_ * T_) / 128;    // 5376
    const int colb0  = w * 16 + 2 * tg;    // nt adds +8
    const int lrow   = tid >> 1;           // feats row this thread loads
    const int lhalf  = tid & 1;            // k half (32 floats)

    // prefetch first tile into registers
    float2 fv[16];
    {
        int t0 = blockIdx.x >> 5, bb0 = (blockIdx.x & 31) * 128;
        const float* src = feats + ((size_t)(bb0 + lrow) * T_ + t0) * D_ + lhalf * 32;
        #pragma unroll
        for (int i = 0; i < 16; i++) fv[i] = *(const float2*)(src + 2 * i);
    }

    for (int til = blockIdx.x; til < NTILES; til += 148) {
        const int t  = til >> 5;
        const int bb = (til & 31) * 128;

        // convert prefetched feats -> bf16 hi/lo images
        #pragma unroll
        for (int i = 0; i < 16; i++) {
            __nv_bfloat162 hh = __floats2bfloat162_rn(fv[i].x, fv[i].y);
            float l0 = fv[i].x - __bfloat162float(__low2bfloat16(hh));
            float l1 = fv[i].y - __bfloat162float(__high2bfloat16(hh));
            __nv_bfloat162 ll = __floats2bfloat162_rn(l0, l1);
            int boff = lrow * 136 + lhalf * 64 + i * 4;
            *(uint32_t*)(smemA + GA_HI + boff) = *(uint32_t*)&hh;
            *(uint32_t*)(smemA + GA_LO + boff) = *(uint32_t*)&ll;
        }
        __syncthreads();

        // issue next tile's LDGs now (retire under the MMAs below)
        int tn = til + 148;
        if (tn < NTILES) {
            int t1 = tn >> 5, b1 = (tn & 31) * 128;
            const float* src = feats + ((size_t)(b1 + lrow) * T_ + t1) * D_ + lhalf * 32;
            #pragma unroll
            for (int i = 0; i < 16; i++) fv[i] = *(const float2*)(src + 2 * i);
        }

        // MMA: 8 m-tiles x 3 regions x 2 n-tiles x 4 ksteps x 3 products
        #pragma unroll 1
        for (int mt = 0; mt < 8; mt++) {
            float c[3][2][4];
            #pragma unroll
            for (int r = 0; r < 3; r++)
                #pragma unroll
                for (int nt = 0; nt < 2; nt++)
                    #pragma unroll
                    for (int q = 0; q < 4; q++) c[r][nt][q] = 0.f;

            #pragma unroll
            for (int ks = 0; ks < 4; ks++) {
                uint32_t ahi[4], alo[4];
                const char* ph = smemA + GA_HI + (mt * 16 + g) * 136 + ks * 32 + tg * 4;
                ahi[0] = *(const uint32_t*)(ph);
                ahi[1] = *(const uint32_t*)(ph + 8 * 136);
                ahi[2] = *(const uint32_t*)(ph + 16);
                ahi[3] = *(const uint32_t*)(ph + 8 * 136 + 16);
                const char* pl = smemA + GA_LO + (mt * 16 + g) * 136 + ks * 32 + tg * 4;
                alo[0] = *(const uint32_t*)(pl);
                alo[1] = *(const uint32_t*)(pl + 8 * 136);
                alo[2] = *(const uint32_t*)(pl + 16);
                alo[3] = *(const uint32_t*)(pl + 8 * 136 + 16);

                #pragma unroll
                for (int r = 0; r < 3; r++)
                    #pragma unroll
                    for (int nt = 0; nt < 2; nt++) {
                        int fb = (((w * 3 + r) * 2 + nt) * 4 + ks) * 256 + lane * 8;
                        uint2 bhi = *(const uint2*)(smemA + GB_HI + fb);
                        uint2 blo = *(const uint2*)(smemA + GB_LO + fb);
                        MMA_BF16(c[r][nt], ahi, bhi);
                        MMA_BF16(c[r][nt], ahi, blo);
                        MMA_BF16(c[r][nt], alo, bhi);
                    }
            }

            // epilogue: + bias, direct sector-aligned float2 stores
            int row0 = bb + mt * 16 + g;
            #pragma unroll
            for (int r = 0; r < 3; r++)
                #pragma unroll
                for (int nt = 0; nt < 2; nt++) {
                    int col = r * 128 + colb0 + nt * 8;
                    float2 b2 = *(const float2*)(sBias + col);
                    float2 o0 = make_float2(c[r][nt][0] + b2.x, c[r][nt][1] + b2.y);
                    float2 o1 = make_float2(c[r][nt][2] + b2.x, c[r][nt][3] + b2.y);
                    *(float2*)(&g_gx[((size_t)t * B_ + row0) * G_ + col])     = o0;
                    *(float2*)(&g_gx[((size_t)t * B_ + row0 + 8) * G_ + col]) = o1;
                }
        }
        __syncthreads();   // all A-image reads done before next convert
    }
}

// ---------------------------------------------------------------------------
// Kernel B: GRU scan with warp-level bf16 mma.sync (R11 measured: 1.084 ms,
// tensor 45.5%). Unchanged.
// ---------------------------------------------------------------------------
#define SB_HI  0          // W_hh hi fragments (98304 B)
#define SB_LO  98304      // W_hh lo fragments (98304 B)
#define SH_HI  196608     // h hi image, 32 rows x 288 B
#define SH_LO  205824     // h lo image
#define SWY    215040     // wy fp32 [384]
#define SBH    216576     // b_hh fp32 [384]
#define SWO    218112     // Wo fp32 [128]
#define SY     218624     // y fp32 [32]
#define SRED   218752     // 8 x 32 fp32
#define S_TOT  219776

__global__ void __launch_bounds__(256, 1)
scan_kernel(const float* __restrict__ h0, const float* __restrict__ y0,
            const float* __restrict__ W_ih, const float* __restrict__ W_hh,
            const float* __restrict__ b_hh, const float* __restrict__ Wo,
            const float* __restrict__ bo, float* __restrict__ out)
{
    extern __shared__ char smemS[];
    const int tid  = threadIdx.x;
    const int w    = tid >> 5;          // warp 0..7
    const int lane = tid & 31;
    const int g    = lane >> 2;         // 0..7
    const int tg   = lane & 3;          // 0..3
    const int b0   = blockIdx.x * 32;

    float* sWyf = (float*)(smemS + SWY);
    float* sBhf = (float*)(smemS + SBH);
    float* sWof = (float*)(smemS + SWO);
    float* sYf  = (float*)(smemS + SY);
    float* sRf  = (float*)(smemS + SRED);

    for (int idx = tid; idx < G_ * H_; idx += 256) {
        int n = idx >> 7;
        int k = idx & 127;
        float wv = W_hh[idx];
        __nv_bfloat16 h16 = __float2bfloat16(wv);
        float lof = wv - __bfloat162float(h16);
        __nv_bfloat16 l16 = __float2bfloat16(lof);
        int region = n >> 7, off = n & 127;
        int ww = off >> 4, nt = (off >> 3) & 1, n8 = off & 7;
        int kstep = k >> 4, kk = k & 15;
        int reg  = kk >> 3;
        int tgi  = (kk & 7) >> 1;
        int half = kk & 1;
        int ln   = n8 * 4 + tgi;
        int fidx = ((ww * 3 + region) * 2 + nt) * 8 + kstep;
        int boff = fidx * 256 + ln * 8 + reg * 4 + half * 2;
        *(unsigned short*)(smemS + SB_HI + boff) = __bfloat16_as_ushort(h16);
        *(unsigned short*)(smemS + SB_LO + boff) = __bfloat16_as_ushort(l16);
    }
    for (int i = tid; i < 32 * H_; i += 256) {
        int row = i >> 7, k = i & 127;
        float hv = h0[(size_t)b0 * H_ + i];
        __nv_bfloat16 h16 = __float2bfloat16(hv);
        float lof = hv - __bfloat162float(h16);
        *(unsigned short*)(smemS + SH_HI + row * 288 + k * 2) = __bfloat16_as_ushort(h16);
        *(unsigned short*)(smemS + SH_LO + row * 288 + k * 2) =
            __bfloat16_as_ushort(__float2bfloat16(lof));
    }
    for (int i = tid; i < G_; i += 256) {
        sWyf[i] = W_ih[(size_t)i * (D_ + 1) + D_];
        sBhf[i] = b_hh[i];
    }
    for (int i = tid; i < H_; i += 256) sWof[i] = Wo[i];
    if (tid < 32) sYf[tid] = y0[b0 + tid];
    const float bo_v = bo[0];
    __syncthreads();

    const int colb0 = w * 16 + 2 * tg;

    for (int t = 0; t < T_; t++) {
        const float* gx = g_gx + ((size_t)t * B_ + b0) * G_;

        float2 xg[3][2][2][2];
        #pragma unroll
        for (int region = 0; region < 3; region++)
            #pragma unroll
            for (int mt = 0; mt < 2; mt++)
                #pragma unroll
                for (int rr = 0; rr < 2; rr++)
                    #pragma unroll
                    for (int nt = 0; nt < 2; nt++) {
                        int row = mt * 16 + rr * 8 + g;
                        xg[region][mt][rr][nt] = *(const float2*)(
                            gx + (size_t)row * G_ + region * 128 + colb0 + nt * 8);
                    }

        float c[2][3][2][4];
        #pragma unroll
        for (int mt = 0; mt < 2; mt++)
            #pragma unroll
            for (int region = 0; region < 3; region++)
                #pragma unroll
                for (int nt = 0; nt < 2; nt++)
                    #pragma unroll
                    for (int q = 0; q < 4; q++) c[mt][region][nt][q] = 0.f;

        #pragma unroll 2
        for (int ks = 0; ks < 8; ks++) {
            uint32_t ahi[2][4], alo[2][4];
            #pragma unroll
            for (int mt = 0; mt < 2; mt++) {
                const char* ph = smemS + SH_HI + (mt * 16 + g) * 288 + ks * 32 + tg * 4;
                ahi[mt][0] = *(const uint32_t*)(ph);
                ahi[mt][1] = *(const uint32_t*)(ph + 8 * 288);
                ahi[mt][2] = *(const uint32_t*)(ph + 16);
                ahi[mt][3] = *(const uint32_t*)(ph + 8 * 288 + 16);
                const char* pl = smemS + SH_LO + (mt * 16 + g) * 288 + ks * 32 + tg * 4;
                alo[mt][0] = *(const uint32_t*)(pl);
                alo[mt][1] = *(const uint32_t*)(pl + 8 * 288);
                alo[mt][2] = *(const uint32_t*)(pl + 16);
                alo[mt][3] = *(const uint32_t*)(pl + 8 * 288 + 16);
            }
            #pragma unroll
            for (int region = 0; region < 3; region++)
                #pragma unroll
                for (int nt = 0; nt < 2; nt++) {
                    int fb = (((w * 3 + region) * 2 + nt) * 8 + ks) * 256 + lane * 8;
                    uint2 bhi = *(const uint2*)(smemS + SB_HI + fb);
                    uint2 blo = *(const uint2*)(smemS + SB_LO + fb);
                    #pragma unroll
                    for (int mt = 0; mt < 2; mt++) {
                        MMA_BF16(c[mt][region][nt], ahi[mt], bhi);
                        MMA_BF16(c[mt][region][nt], ahi[mt], blo);
                        MMA_BF16(c[mt][region][nt], alo[mt], bhi);
                        MMA_BF16(c[mt][region][nt], alo[mt], blo);
                    }
                }
        }

        float2 wyc[3][2], bhc[3][2], woc[2];
        #pragma unroll
        for (int region = 0; region < 3; region++)
            #pragma unroll
            for (int nt = 0; nt < 2; nt++) {
                wyc[region][nt] = *(const float2*)(sWyf + region * 128 + colb0 + nt * 8);
                bhc[region][nt] = *(const float2*)(sBhf + region * 128 + colb0 + nt * 8);
            }
        woc[0] = *(const float2*)(sWof + colb0);
        woc[1] = *(const float2*)(sWof + colb0 + 8);

        float pacc[4] = {0.f, 0.f, 0.f, 0.f};
        uint32_t hhiN[2][2][2], hloN[2][2][2];
        #pragma unroll
        for (int mt = 0; mt < 2; mt++)
            #pragma unroll
            for (int rr = 0; rr < 2; rr++) {
                int row = mt * 16 + rr * 8 + g;
                float y = sYf[row];
                #pragma unroll
                for (int nt = 0; nt < 2; nt++) {
                    int cb = (colb0 + nt * 8) * 2;
                    uint32_t hpw = *(const uint32_t*)(smemS + SH_HI + row * 288 + cb);
                    uint32_t lpw = *(const uint32_t*)(smemS + SH_LO + row * 288 + cb);
                    float hp0 = __bfloat162float(__ushort_as_bfloat16((unsigned short)(hpw)))
                              + __bfloat162float(__ushort_as_bfloat16((unsigned short)(lpw)));
                    float hp1 = __bfloat162float(__ushort_as_bfloat16((unsigned short)(hpw >> 16)))
                              + __bfloat162float(__ushort_as_bfloat16((unsigned short)(lpw >> 16)));

                    int i0 = rr * 2;
                    float r0 = fast_sigmoid(xg[0][mt][rr][nt].x + y * wyc[0][nt].x + bhc[0][nt].x + c[mt][0][nt][i0]);
                    float z0 = fast_sigmoid(xg[1][mt][rr][nt].x + y * wyc[1][nt].x + bhc[1][nt].x + c[mt][1][nt][i0]);
                    float n0 = fast_tanh  (xg[2][mt][rr][nt].x + y * wyc[2][nt].x + r0 * (bhc[2][nt].x + c[mt][2][nt][i0]));
                    float h0v = (1.f - z0) * n0 + z0 * hp0;

                    float r1 = fast_sigmoid(xg[0][mt][rr][nt].y + y * wyc[0][nt].y + bhc[0][nt].y + c[mt][0][nt][i0 + 1]);
                    float z1 = fast_sigmoid(xg[1][mt][rr][nt].y + y * wyc[1][nt].y + bhc[1][nt].y + c[mt][1][nt][i0 + 1]);
                    float n1 = fast_tanh  (xg[2][mt][rr][nt].y + y * wyc[2][nt].y + r1 * (bhc[2][nt].y + c[mt][2][nt][i0 + 1]));
                    float h1v = (1.f - z1) * n1 + z1 * hp1;

                    pacc[mt * 2 + rr] += h0v * woc[nt].x + h1v * woc[nt].y;

                    __nv_bfloat16 hb0 = __float2bfloat16(h0v);
                    __nv_bfloat16 hb1 = __float2bfloat16(h1v);
                    float l0 = h0v - __bfloat162float(hb0);
                    float l1 = h1v - __bfloat162float(hb1);
                    __nv_bfloat16 lb0 = __float2bfloat16(l0);
                    __nv_bfloat16 lb1 = __float2bfloat16(l1);
                    hhiN[mt][rr][nt] = (uint32_t)__bfloat16_as_ushort(hb0)
                                     | ((uint32_t)__bfloat16_as_ushort(hb1) << 16);
                    hloN[mt][rr][nt] = (uint32_t)__bfloat16_as_ushort(lb0)
                                     | ((uint32_t)__bfloat16_as_ushort(lb1) << 16);
                }
            }
        __syncthreads();

        #pragma unroll
        for (int mt = 0; mt < 2; mt++)
            #pragma unroll
            for (int rr = 0; rr < 2; rr++) {
                int row = mt * 16 + rr * 8 + g;
                #pragma unroll
                for (int nt = 0; nt < 2; nt++) {
                    int cb = (colb0 + nt * 8) * 2;
                    *(uint32_t*)(smemS + SH_HI + row * 288 + cb) = hhiN[mt][rr][nt];
                    *(uint32_t*)(smemS + SH_LO + row * 288 + cb) = hloN[mt][rr][nt];
                }
            }

        #pragma unroll
        for (int i = 0; i < 4; i++) {
            pacc[i] += __shfl_xor_sync(0xffffffffu, pacc[i], 1);
            pacc[i] += __shfl_xor_sync(0xffffffffu, pacc[i], 2);
        }
        if (tg == 0) {
            sRf[w * 32 + g]      = pacc[0];
            sRf[w * 32 + g + 8]  = pacc[1];
            sRf[w * 32 + g + 16] = pacc[2];
            sRf[w * 32 + g + 24] = pacc[3];
        }
        __syncthreads();
        if (tid < 32) {
            float s = bo_v;
            #pragma unroll
            for (int ww = 0; ww < 8; ww++) s += sRf[ww * 32 + tid];
            sYf[tid] = s;
            out[(size_t)(b0 + tid) * T_ + t] = s;
        }
        __syncthreads();
    }
}

// ---------------------------------------------------------------------------
extern "C" void kernel_launch(void* const* d_in, const int* in_sizes, int n_in,
                              void* d_out, int out_size)
{
    const float* feats = (const float*)d_in[0];
    const float* h0    = (const float*)d_in[1];
    const float* y0    = (const float*)d_in[2];
    const float* W_ih  = (const float*)d_in[3];
    const float* W_hh  = (const float*)d_in[4];
    const float* b_ih  = (const float*)d_in[5];
    const float* b_hh  = (const float*)d_in[6];
    const float* Wo    = (const float*)d_in[7];
    const float* bo    = (const float*)d_in[8];
    float* out = (float*)d_out;

    cudaFuncSetAttribute(gx_kernel, cudaFuncAttributeMaxDynamicSharedMemorySize, G_TOT);
    gx_kernel<<<148, 256, G_TOT>>>(feats, W_ih, b_ih);

    cudaFuncSetAttribute(scan_kernel, cudaFuncAttributeMaxDynamicSharedMemorySize, S_TOT);
    scan_kernel<<<B_ / 32, 256, S_TOT>>>(h0, y0, W_ih, W_hh, b_hh, Wo, bo, out);
}

// round 13
// speedup vs baseline: 2.0301x; 1.0411x over previous
#include <cuda_runtime.h>
#include <cuda_bf16.h>
#include <cstdint>
#include <cstddef>

#define B_ 4096
#define T_ 168
#define D_ 64
#define H_ 128
#define G_ 384   // 3*H

// ---------------------------------------------------------------------------
// helpers
// ---------------------------------------------------------------------------
__device__ __forceinline__ float fast_sigmoid(float x) {
    return __fdividef(1.f, 1.f + __expf(-x));
}
__device__ __forceinline__ float fast_tanh(float x) {
    return __fdividef(2.f, 1.f + __expf(-2.f * x)) - 1.f;
}

// warp-level bf16 tensor-core mma (HMMA path, plain sm_100-legal PTX)
#define MMA_BF16(c, a, b) \
    asm volatile("mma.sync.aligned.m16n8k16.row.col.f32.bf16.bf16.f32 " \
        "{%0,%1,%2,%3}, {%4,%5,%6,%7}, {%8,%9}, {%0,%1,%2,%3};" \
        : "+f"((c)[0]), "+f"((c)[1]), "+f"((c)[2]), "+f"((c)[3]) \
        : "r"((a)[0]), "r"((a)[1]), "r"((a)[2]), "r"((a)[3]), \
          "r"((b).x), "r"((b).y))

// Scratch: gx[t][b][g] fp32, ~1.01 GB device global.
__device__ float g_gx[(size_t)T_ * B_ * G_];

// ---------------------------------------------------------------------------
// Kernel A (R12 measured, ~0.47 ms): mma.sync bf16, 3-product split.
// Unchanged.
// ---------------------------------------------------------------------------
#define GB_HI  0                      // W_ih hi fragments (49152 B)
#define GB_LO  49152                  // W_ih lo fragments (49152 B)
#define GA_HI  98304                  // feats hi image 128 x 136 B
#define GA_LO  (98304 + 17408)
#define GBIAS  (98304 + 34816)        // 384 f32
#define G_TOT  (GBIAS + 1536)

__global__ void __launch_bounds__(256, 1)
gx_kernel(const float* __restrict__ feats, const float* __restrict__ W_ih,
          const float* __restrict__ b_ih)
{
    extern __shared__ char smemA[];
    const int tid  = threadIdx.x;
    const int w    = tid >> 5;
    const int lane = tid & 31;
    const int g    = lane >> 2;
    const int tg   = lane & 3;

    float* sBias = (float*)(smemA + GBIAS);

    for (int idx = tid; idx < G_ * D_; idx += 256) {
        int n = idx >> 6;
        int k = idx & 63;
        float wv = W_ih[(size_t)n * (D_ + 1) + k];
        __nv_bfloat16 h16 = __float2bfloat16(wv);
        float lof = wv - __bfloat162float(h16);
        __nv_bfloat16 l16 = __float2bfloat16(lof);
        int region = n >> 7, off = n & 127;
        int ww = off >> 4, nt = (off >> 3) & 1, n8 = off & 7;
        int kstep = k >> 4, kk = k & 15;
        int reg  = kk >> 3;
        int tgi  = (kk & 7) >> 1;
        int half = kk & 1;
        int ln   = n8 * 4 + tgi;
        int fidx = ((ww * 3 + region) * 2 + nt) * 4 + kstep;
        int boff = fidx * 256 + ln * 8 + reg * 4 + half * 2;
        *(unsigned short*)(smemA + GB_HI + boff) = __bfloat16_as_ushort(h16);
        *(unsigned short*)(smemA + GB_LO + boff) = __bfloat16_as_ushort(l16);
    }
    for (int i = tid; i < G_; i += 256) sBias[i] = b_ih[i];
    __syncthreads();

    const int NTILES = (B_ * T_) / 128;    // 5376
    const int colb0  = w * 16 + 2 * tg;
    const int lrow   = tid >> 1;
    const int lhalf  = tid & 1;

    float2 fv[16];
    {
        int t0 = blockIdx.x >> 5, bb0 = (blockIdx.x & 31) * 128;
        const float* src = feats + ((size_t)(bb0 + lrow) * T_ + t0) * D_ + lhalf * 32;
        #pragma unroll
        for (int i = 0; i < 16; i++) fv[i] = *(const float2*)(src + 2 * i);
    }

    for (int til = blockIdx.x; til < NTILES; til += 148) {
        const int t  = til >> 5;
        const int bb = (til & 31) * 128;

        #pragma unroll
        for (int i = 0; i < 16; i++) {
            __nv_bfloat162 hh = __floats2bfloat162_rn(fv[i].x, fv[i].y);
            float l0 = fv[i].x - __bfloat162float(__low2bfloat16(hh));
            float l1 = fv[i].y - __bfloat162float(__high2bfloat16(hh));
            __nv_bfloat162 ll = __floats2bfloat162_rn(l0, l1);
            int boff = lrow * 136 + lhalf * 64 + i * 4;
            *(uint32_t*)(smemA + GA_HI + boff) = *(uint32_t*)&hh;
            *(uint32_t*)(smemA + GA_LO + boff) = *(uint32_t*)&ll;
        }
        __syncthreads();

        int tn = til + 148;
        if (tn < NTILES) {
            int t1 = tn >> 5, b1 = (tn & 31) * 128;
            const float* src = feats + ((size_t)(b1 + lrow) * T_ + t1) * D_ + lhalf * 32;
            #pragma unroll
            for (int i = 0; i < 16; i++) fv[i] = *(const float2*)(src + 2 * i);
        }

        #pragma unroll 1
        for (int mt = 0; mt < 8; mt++) {
            float c[3][2][4];
            #pragma unroll
            for (int r = 0; r < 3; r++)
                #pragma unroll
                for (int nt = 0; nt < 2; nt++)
                    #pragma unroll
                    for (int q = 0; q < 4; q++) c[r][nt][q] = 0.f;

            #pragma unroll
            for (int ks = 0; ks < 4; ks++) {
                uint32_t ahi[4], alo[4];
                const char* ph = smemA + GA_HI + (mt * 16 + g) * 136 + ks * 32 + tg * 4;
                ahi[0] = *(const uint32_t*)(ph);
                ahi[1] = *(const uint32_t*)(ph + 8 * 136);
                ahi[2] = *(const uint32_t*)(ph + 16);
                ahi[3] = *(const uint32_t*)(ph + 8 * 136 + 16);
                const char* pl = smemA + GA_LO + (mt * 16 + g) * 136 + ks * 32 + tg * 4;
                alo[0] = *(const uint32_t*)(pl);
                alo[1] = *(const uint32_t*)(pl + 8 * 136);
                alo[2] = *(const uint32_t*)(pl + 16);
                alo[3] = *(const uint32_t*)(pl + 8 * 136 + 16);

                #pragma unroll
                for (int r = 0; r < 3; r++)
                    #pragma unroll
                    for (int nt = 0; nt < 2; nt++) {
                        int fb = (((w * 3 + r) * 2 + nt) * 4 + ks) * 256 + lane * 8;
                        uint2 bhi = *(const uint2*)(smemA + GB_HI + fb);
                        uint2 blo = *(const uint2*)(smemA + GB_LO + fb);
                        MMA_BF16(c[r][nt], ahi, bhi);
                        MMA_BF16(c[r][nt], ahi, blo);
                        MMA_BF16(c[r][nt], alo, bhi);
                    }
            }

            int row0 = bb + mt * 16 + g;
            #pragma unroll
            for (int r = 0; r < 3; r++)
                #pragma unroll
                for (int nt = 0; nt < 2; nt++) {
                    int col = r * 128 + colb0 + nt * 8;
                    float2 b2 = *(const float2*)(sBias + col);
                    float2 o0 = make_float2(c[r][nt][0] + b2.x, c[r][nt][1] + b2.y);
                    float2 o1 = make_float2(c[r][nt][2] + b2.x, c[r][nt][3] + b2.y);
                    *(float2*)(&g_gx[((size_t)t * B_ + row0) * G_ + col])     = o0;
                    *(float2*)(&g_gx[((size_t)t * B_ + row0 + 8) * G_ + col]) = o1;
                }
        }
        __syncthreads();
    }
}

// ---------------------------------------------------------------------------
// Kernel B: GRU scan, mma.sync bf16 — now 512 threads (16 warps, 4/SMSP).
// Warp (wm = w>>3) owns m-half (16 of 32 rows); (wn = w&7) owns the same
// column group as before -> B-fragment table identical to R11/R12.
// Split reduced to 3 products (lo.lo ~2^-18, dropped).
// Per warp per step: 8 ks x 3 regions x 2 nt x 3 products = 144 mma.
// ---------------------------------------------------------------------------
#define SB_HI  0          // W_hh hi fragments (98304 B)
#define SB_LO  98304      // W_hh lo fragments (98304 B)
#define SH_HI  196608     // h hi image, 32 rows x 288 B
#define SH_LO  205824     // h lo image
#define SWY    215040     // wy fp32 [384]
#define SBH    216576     // b_hh fp32 [384]
#define SWO    218112     // Wo fp32 [128]
#define SY     218624     // y fp32 [32]
#define SRED   218752     // 8 x 32 fp32 (indexed by wn slice)
#define S_TOT  219776

__global__ void __launch_bounds__(512, 1)
scan_kernel(const float* __restrict__ h0, const float* __restrict__ y0,
            const float* __restrict__ W_ih, const float* __restrict__ W_hh,
            const float* __restrict__ b_hh, const float* __restrict__ Wo,
            const float* __restrict__ bo, float* __restrict__ out)
{
    extern __shared__ char smemS[];
    const int tid  = threadIdx.x;
    const int w    = tid >> 5;          // warp 0..15
    const int wm   = w >> 3;            // m-half 0..1
    const int wn   = w & 7;             // column warp-group 0..7
    const int lane = tid & 31;
    const int g    = lane >> 2;         // 0..7
    const int tg   = lane & 3;          // 0..3
    const int b0   = blockIdx.x * 32;

    float* sWyf = (float*)(smemS + SWY);
    float* sBhf = (float*)(smemS + SBH);
    float* sWof = (float*)(smemS + SWO);
    float* sYf  = (float*)(smemS + SY);
    float* sRf  = (float*)(smemS + SRED);

    // ---- init: W_hh -> bf16 hi/lo fragments (identical layout to R11) ----
    for (int idx = tid; idx < G_ * H_; idx += 512) {
        int n = idx >> 7;
        int k = idx & 127;
        float wv = W_hh[idx];
        __nv_bfloat16 h16 = __float2bfloat16(wv);
        float lof = wv - __bfloat162float(h16);
        __nv_bfloat16 l16 = __float2bfloat16(lof);
        int region = n >> 7, off = n & 127;
        int ww = off >> 4, nt = (off >> 3) & 1, n8 = off & 7;
        int kstep = k >> 4, kk = k & 15;
        int reg  = kk >> 3;
        int tgi  = (kk & 7) >> 1;
        int half = kk & 1;
        int ln   = n8 * 4 + tgi;
        int fidx = ((ww * 3 + region) * 2 + nt) * 8 + kstep;
        int boff = fidx * 256 + ln * 8 + reg * 4 + half * 2;
        *(unsigned short*)(smemS + SB_HI + boff) = __bfloat16_as_ushort(h16);
        *(unsigned short*)(smemS + SB_LO + boff) = __bfloat16_as_ushort(l16);
    }
    for (int i = tid; i < 32 * H_; i += 512) {
        int row = i >> 7, k = i & 127;
        float hv = h0[(size_t)b0 * H_ + i];
        __nv_bfloat16 h16 = __float2bfloat16(hv);
        float lof = hv - __bfloat162float(h16);
        *(unsigned short*)(smemS + SH_HI + row * 288 + k * 2) = __bfloat16_as_ushort(h16);
        *(unsigned short*)(smemS + SH_LO + row * 288 + k * 2) =
            __bfloat16_as_ushort(__float2bfloat16(lof));
    }
    for (int i = tid; i < G_; i += 512) {
        sWyf[i] = W_ih[(size_t)i * (D_ + 1) + D_];
        sBhf[i] = b_hh[i];
    }
    for (int i = tid; i < H_; i += 512) sWof[i] = Wo[i];
    if (tid < 32) sYf[tid] = y0[b0 + tid];
    const float bo_v = bo[0];
    __syncthreads();

    const int colb0 = wn * 16 + 2 * tg;

    for (int t = 0; t < T_; t++) {
        const float* gx = g_gx + ((size_t)t * B_ + b0) * G_;

        // gx prefetch (consumed in epilogue): [region][rr][nt]
        float2 xg[3][2][2];
        #pragma unroll
        for (int region = 0; region < 3; region++)
            #pragma unroll
            for (int rr = 0; rr < 2; rr++)
                #pragma unroll
                for (int nt = 0; nt < 2; nt++) {
                    int row = wm * 16 + rr * 8 + g;
                    xg[region][rr][nt] = *(const float2*)(
                        gx + (size_t)row * G_ + region * 128 + colb0 + nt * 8);
                }

        float c[3][2][4];
        #pragma unroll
        for (int region = 0; region < 3; region++)
            #pragma unroll
            for (int nt = 0; nt < 2; nt++)
                #pragma unroll
                for (int q = 0; q < 4; q++) c[region][nt][q] = 0.f;

        // ------ tensor-core mainloop (3-product split) ------
        #pragma unroll 2
        for (int ks = 0; ks < 8; ks++) {
            uint32_t ahi[4], alo[4];
            const char* ph = smemS + SH_HI + (wm * 16 + g) * 288 + ks * 32 + tg * 4;
            ahi[0] = *(const uint32_t*)(ph);
            ahi[1] = *(const uint32_t*)(ph + 8 * 288);
            ahi[2] = *(const uint32_t*)(ph + 16);
            ahi[3] = *(const uint32_t*)(ph + 8 * 288 + 16);
            const char* pl = smemS + SH_LO + (wm * 16 + g) * 288 + ks * 32 + tg * 4;
            alo[0] = *(const uint32_t*)(pl);
            alo[1] = *(const uint32_t*)(pl + 8 * 288);
            alo[2] = *(const uint32_t*)(pl + 16);
            alo[3] = *(const uint32_t*)(pl + 8 * 288 + 16);

            #pragma unroll
            for (int region = 0; region < 3; region++)
                #pragma unroll
                for (int nt = 0; nt < 2; nt++) {
                    int fb = (((wn * 3 + region) * 2 + nt) * 8 + ks) * 256 + lane * 8;
                    uint2 bhi = *(const uint2*)(smemS + SB_HI + fb);
                    uint2 blo = *(const uint2*)(smemS + SB_LO + fb);
                    MMA_BF16(c[region][nt], ahi, bhi);
                    MMA_BF16(c[region][nt], ahi, blo);
                    MMA_BF16(c[region][nt], alo, bhi);
                }
        }

        // ------ epilogue: gates + h update ------
        float2 wyc[3][2], bhc[3][2], woc[2];
        #pragma unroll
        for (int region = 0; region < 3; region++)
            #pragma unroll
            for (int nt = 0; nt < 2; nt++) {
                wyc[region][nt] = *(const float2*)(sWyf + region * 128 + colb0 + nt * 8);
                bhc[region][nt] = *(const float2*)(sBhf + region * 128 + colb0 + nt * 8);
            }
        woc[0] = *(const float2*)(sWof + colb0);
        woc[1] = *(const float2*)(sWof + colb0 + 8);

        float pacc[2] = {0.f, 0.f};
        uint32_t hhiN[2][2], hloN[2][2];
        #pragma unroll
        for (int rr = 0; rr < 2; rr++) {
            int row = wm * 16 + rr * 8 + g;
            float y = sYf[row];
            #pragma unroll
            for (int nt = 0; nt < 2; nt++) {
                int cb = (colb0 + nt * 8) * 2;
                uint32_t hpw = *(const uint32_t*)(smemS + SH_HI + row * 288 + cb);
                uint32_t lpw = *(const uint32_t*)(smemS + SH_LO + row * 288 + cb);
                float hp0 = __bfloat162float(__ushort_as_bfloat16((unsigned short)(hpw)))
                          + __bfloat162float(__ushort_as_bfloat16((unsigned short)(lpw)));
                float hp1 = __bfloat162float(__ushort_as_bfloat16((unsigned short)(hpw >> 16)))
                          + __bfloat162float(__ushort_as_bfloat16((unsigned short)(lpw >> 16)));

                int i0 = rr * 2;
                float r0 = fast_sigmoid(xg[0][rr][nt].x + y * wyc[0][nt].x + bhc[0][nt].x + c[0][nt][i0]);
                float z0 = fast_sigmoid(xg[1][rr][nt].x + y * wyc[1][nt].x + bhc[1][nt].x + c[1][nt][i0]);
                float n0 = fast_tanh  (xg[2][rr][nt].x + y * wyc[2][nt].x + r0 * (bhc[2][nt].x + c[2][nt][i0]));
                float h0v = (1.f - z0) * n0 + z0 * hp0;

                float r1 = fast_sigmoid(xg[0][rr][nt].y + y * wyc[0][nt].y + bhc[0][nt].y + c[0][nt][i0 + 1]);
                float z1 = fast_sigmoid(xg[1][rr][nt].y + y * wyc[1][nt].y + bhc[1][nt].y + c[1][nt][i0 + 1]);
                float n1 = fast_tanh  (xg[2][rr][nt].y + y * wyc[2][nt].y + r1 * (bhc[2][nt].y + c[2][nt][i0 + 1]));
                float h1v = (1.f - z1) * n1 + z1 * hp1;

                pacc[rr] += h0v * woc[nt].x + h1v * woc[nt].y;

                __nv_bfloat16 hb0 = __float2bfloat16(h0v);
                __nv_bfloat16 hb1 = __float2bfloat16(h1v);
                float l0 = h0v - __bfloat162float(hb0);
                float l1 = h1v - __bfloat162float(hb1);
                hhiN[rr][nt] = (uint32_t)__bfloat16_as_ushort(hb0)
                             | ((uint32_t)__bfloat16_as_ushort(hb1) << 16);
                hloN[rr][nt] = (uint32_t)__bfloat16_as_ushort(__float2bfloat16(l0))
                             | ((uint32_t)__bfloat16_as_ushort(__float2bfloat16(l1)) << 16);
            }
        }
        __syncthreads();   // all reads of sH done block-wide

        #pragma unroll
        for (int rr = 0; rr < 2; rr++) {
            int row = wm * 16 + rr * 8 + g;
            #pragma unroll
            for (int nt = 0; nt < 2; nt++) {
                int cb = (colb0 + nt * 8) * 2;
                *(uint32_t*)(smemS + SH_HI + row * 288 + cb) = hhiN[rr][nt];
                *(uint32_t*)(smemS + SH_LO + row * 288 + cb) = hloN[rr][nt];
            }
        }

        // y reduction: fold tg lanes; warps (wm,wn) write disjoint rows of
        // slice wn; final sum over the 8 wn slices.
        #pragma unroll
        for (int i = 0; i < 2; i++) {
            pacc[i] += __shfl_xor_sync(0xffffffffu, pacc[i], 1);
            pacc[i] += __shfl_xor_sync(0xffffffffu, pacc[i], 2);
        }
        if (tg == 0) {
            sRf[wn * 32 + wm * 16 + g]     = pacc[0];
            sRf[wn * 32 + wm * 16 + g + 8] = pacc[1];
        }
        __syncthreads();
        if (tid < 32) {
            float s = bo_v;
            #pragma unroll
            for (int ww = 0; ww < 8; ww++) s += sRf[ww * 32 + tid];
            sYf[tid] = s;
            out[(size_t)(b0 + tid) * T_ + t] = s;
        }
        __syncthreads();
    }
}

// ---------------------------------------------------------------------------
extern "C" void kernel_launch(void* const* d_in, const int* in_sizes, int n_in,
                              void* d_out, int out_size)
{
    const float* feats = (const float*)d_in[0];
    const float* h0    = (const float*)d_in[1];
    const float* y0    = (const float*)d_in[2];
    const float* W_ih  = (const float*)d_in[3];
    const float* W_hh  = (const float*)d_in[4];
    const float* b_ih  = (const float*)d_in[5];
    const float* b_hh  = (const float*)d_in[6];
    const float* Wo    = (const float*)d_in[7];
    const float* bo    = (const float*)d_in[8];
    float* out = (float*)d_out;

    cudaFuncSetAttribute(gx_kernel, cudaFuncAttributeMaxDynamicSharedMemorySize, G_TOT);
    gx_kernel<<<148, 256, G_TOT>>>(feats, W_ih, b_ih);

    cudaFuncSetAttribute(scan_kernel, cudaFuncAttributeMaxDynamicSharedMemorySize, S_TOT);
    scan_kernel<<<B_ / 32, 512, S_TOT>>>(h0, y0, W_ih, W_hh, b_hh, Wo, bo, out);
}

// round 14
// speedup vs baseline: 2.1981x; 1.0827x over previous
#include <cuda_runtime.h>
#include <cuda_bf16.h>
#include <cstdint>
#include <cstddef>

#define B_ 4096
#define T_ 168
#define D_ 64
#define H_ 128
#define G_ 384   // 3*H

// ---------------------------------------------------------------------------
// helpers
// ---------------------------------------------------------------------------
__device__ __forceinline__ float fast_sigmoid(float x) {
    return __fdividef(1.f, 1.f + __expf(-x));
}
__device__ __forceinline__ float fast_tanh(float x) {
    return __fdividef(2.f, 1.f + __expf(-2.f * x)) - 1.f;
}

// warp-level bf16 tensor-core mma (HMMA path, plain sm_100-legal PTX)
#define MMA_BF16(c, a, b) \
    asm volatile("mma.sync.aligned.m16n8k16.row.col.f32.bf16.bf16.f32 " \
        "{%0,%1,%2,%3}, {%4,%5,%6,%7}, {%8,%9}, {%0,%1,%2,%3};" \
        : "+f"((c)[0]), "+f"((c)[1]), "+f"((c)[2]), "+f"((c)[3]) \
        : "r"((a)[0]), "r"((a)[1]), "r"((a)[2]), "r"((a)[3]), \
          "r"((b).x), "r"((b).y))

// Scratch: gx[t][b][g] fp32, ~1.01 GB device global.
__device__ float g_gx[(size_t)T_ * B_ * G_];

// ---------------------------------------------------------------------------
// Kernel A: mma.sync bf16, 3-product split. A-image pad 136 -> 144 B
// (36 words = 4 banks/row -> fragment loads conflict-free).
// ---------------------------------------------------------------------------
#define GB_HI  0                      // W_ih hi fragments (49152 B)
#define GB_LO  49152                  // W_ih lo fragments (49152 B)
#define GA_HI  98304                  // feats hi image 128 x 144 B
#define GA_LO  (98304 + 18432)
#define GBIAS  (98304 + 36864)        // 384 f32
#define G_TOT  (GBIAS + 1536)

__global__ void __launch_bounds__(256, 1)
gx_kernel(const float* __restrict__ feats, const float* __restrict__ W_ih,
          const float* __restrict__ b_ih)
{
    extern __shared__ char smemA[];
    const int tid  = threadIdx.x;
    const int w    = tid >> 5;
    const int lane = tid & 31;
    const int g    = lane >> 2;
    const int tg   = lane & 3;

    float* sBias = (float*)(smemA + GBIAS);

    for (int idx = tid; idx < G_ * D_; idx += 256) {
        int n = idx >> 6;
        int k = idx & 63;
        float wv = W_ih[(size_t)n * (D_ + 1) + k];
        __nv_bfloat16 h16 = __float2bfloat16(wv);
        float lof = wv - __bfloat162float(h16);
        __nv_bfloat16 l16 = __float2bfloat16(lof);
        int region = n >> 7, off = n & 127;
        int ww = off >> 4, nt = (off >> 3) & 1, n8 = off & 7;
        int kstep = k >> 4, kk = k & 15;
        int reg  = kk >> 3;
        int tgi  = (kk & 7) >> 1;
        int half = kk & 1;
        int ln   = n8 * 4 + tgi;
        int fidx = ((ww * 3 + region) * 2 + nt) * 4 + kstep;
        int boff = fidx * 256 + ln * 8 + reg * 4 + half * 2;
        *(unsigned short*)(smemA + GB_HI + boff) = __bfloat16_as_ushort(h16);
        *(unsigned short*)(smemA + GB_LO + boff) = __bfloat16_as_ushort(l16);
    }
    for (int i = tid; i < G_; i += 256) sBias[i] = b_ih[i];
    __syncthreads();

    const int NTILES = (B_ * T_) / 128;    // 5376
    const int colb0  = w * 16 + 2 * tg;
    const int lrow   = tid >> 1;
    const int lhalf  = tid & 1;

    float2 fv[16];
    {
        int t0 = blockIdx.x >> 5, bb0 = (blockIdx.x & 31) * 128;
        const float* src = feats + ((size_t)(bb0 + lrow) * T_ + t0) * D_ + lhalf * 32;
        #pragma unroll
        for (int i = 0; i < 16; i++) fv[i] = *(const float2*)(src + 2 * i);
    }

    for (int til = blockIdx.x; til < NTILES; til += 148) {
        const int t  = til >> 5;
        const int bb = (til & 31) * 128;

        #pragma unroll
        for (int i = 0; i < 16; i++) {
            __nv_bfloat162 hh = __floats2bfloat162_rn(fv[i].x, fv[i].y);
            float l0 = fv[i].x - __bfloat162float(__low2bfloat16(hh));
            float l1 = fv[i].y - __bfloat162float(__high2bfloat16(hh));
            __nv_bfloat162 ll = __floats2bfloat162_rn(l0, l1);
            int boff = lrow * 144 + lhalf * 64 + i * 4;
            *(uint32_t*)(smemA + GA_HI + boff) = *(uint32_t*)&hh;
            *(uint32_t*)(smemA + GA_LO + boff) = *(uint32_t*)&ll;
        }
        __syncthreads();

        int tn = til + 148;
        if (tn < NTILES) {
            int t1 = tn >> 5, b1 = (tn & 31) * 128;
            const float* src = feats + ((size_t)(b1 + lrow) * T_ + t1) * D_ + lhalf * 32;
            #pragma unroll
            for (int i = 0; i < 16; i++) fv[i] = *(const float2*)(src + 2 * i);
        }

        #pragma unroll 1
        for (int mt = 0; mt < 8; mt++) {
            float c[3][2][4];
            #pragma unroll
            for (int r = 0; r < 3; r++)
                #pragma unroll
                for (int nt = 0; nt < 2; nt++)
                    #pragma unroll
                    for (int q = 0; q < 4; q++) c[r][nt][q] = 0.f;

            #pragma unroll
            for (int ks = 0; ks < 4; ks++) {
                uint32_t ahi[4], alo[4];
                const char* ph = smemA + GA_HI + (mt * 16 + g) * 144 + ks * 32 + tg * 4;
                ahi[0] = *(const uint32_t*)(ph);
                ahi[1] = *(const uint32_t*)(ph + 8 * 144);
                ahi[2] = *(const uint32_t*)(ph + 16);
                ahi[3] = *(const uint32_t*)(ph + 8 * 144 + 16);
                const char* pl = smemA + GA_LO + (mt * 16 + g) * 144 + ks * 32 + tg * 4;
                alo[0] = *(const uint32_t*)(pl);
                alo[1] = *(const uint32_t*)(pl + 8 * 144);
                alo[2] = *(const uint32_t*)(pl + 16);
                alo[3] = *(const uint32_t*)(pl + 8 * 144 + 16);

                #pragma unroll
                for (int r = 0; r < 3; r++)
                    #pragma unroll
                    for (int nt = 0; nt < 2; nt++) {
                        int fb = (((w * 3 + r) * 2 + nt) * 4 + ks) * 256 + lane * 8;
                        uint2 bhi = *(const uint2*)(smemA + GB_HI + fb);
                        uint2 blo = *(const uint2*)(smemA + GB_LO + fb);
                        MMA_BF16(c[r][nt], ahi, bhi);
                        MMA_BF16(c[r][nt], ahi, blo);
                        MMA_BF16(c[r][nt], alo, bhi);
                    }
            }

            int row0 = bb + mt * 16 + g;
            #pragma unroll
            for (int r = 0; r < 3; r++)
                #pragma unroll
                for (int nt = 0; nt < 2; nt++) {
                    int col = r * 128 + colb0 + nt * 8;
                    float2 b2 = *(const float2*)(sBias + col);
                    float2 o0 = make_float2(c[r][nt][0] + b2.x, c[r][nt][1] + b2.y);
                    float2 o1 = make_float2(c[r][nt][2] + b2.x, c[r][nt][3] + b2.y);
                    *(float2*)(&g_gx[((size_t)t * B_ + row0) * G_ + col])     = o0;
                    *(float2*)(&g_gx[((size_t)t * B_ + row0 + 8) * G_ + col]) = o1;
                }
        }
        __syncthreads();
    }
}

// ---------------------------------------------------------------------------
// Kernel B: GRU scan, mma.sync bf16, 256 threads (8 warps), 3-product
// split. B-hi fragments (48 uint2 = 96 regs) persistent in REGISTERS for
// all 168 steps; only B-lo streams from smem -> halves B crossbar traffic.
// h image pad 272 B (68 words = 4 banks/row): A-fragment LDS conflict-free.
// ---------------------------------------------------------------------------
#define SB_HI  0          // W_hh hi fragments (98304 B) — staging for reg load
#define SB_LO  98304      // W_hh lo fragments (98304 B)
#define SH_HI  196608     // h hi image, 32 rows x 272 B
#define SH_LO  205312     // h lo image
#define SWY    214016     // wy fp32 [384]
#define SBH    215552     // b_hh fp32 [384]
#define SWO    217088     // Wo fp32 [128]
#define SY     217600     // y fp32 [32]
#define SRED   217728     // 8 x 32 fp32
#define S_TOT  218752

__global__ void __launch_bounds__(256, 1)
scan_kernel(const float* __restrict__ h0, const float* __restrict__ y0,
            const float* __restrict__ W_ih, const float* __restrict__ W_hh,
            const float* __restrict__ b_hh, const float* __restrict__ Wo,
            const float* __restrict__ bo, float* __restrict__ out)
{
    extern __shared__ char smemS[];
    const int tid  = threadIdx.x;
    const int w    = tid >> 5;          // warp 0..7 (column group)
    const int lane = tid & 31;
    const int g    = lane >> 2;         // 0..7
    const int tg   = lane & 3;          // 0..3
    const int b0   = blockIdx.x * 32;

    float* sWyf = (float*)(smemS + SWY);
    float* sBhf = (float*)(smemS + SBH);
    float* sWof = (float*)(smemS + SWO);
    float* sYf  = (float*)(smemS + SY);
    float* sRf  = (float*)(smemS + SRED);

    // ---- init: W_hh -> bf16 hi/lo fragments ----
    for (int idx = tid; idx < G_ * H_; idx += 256) {
        int n = idx >> 7;
        int k = idx & 127;
        float wv = W_hh[idx];
        __nv_bfloat16 h16 = __float2bfloat16(wv);
        float lof = wv - __bfloat162float(h16);
        __nv_bfloat16 l16 = __float2bfloat16(lof);
        int region = n >> 7, off = n & 127;
        int ww = off >> 4, nt = (off >> 3) & 1, n8 = off & 7;
        int kstep = k >> 4, kk = k & 15;
        int reg  = kk >> 3;
        int tgi  = (kk & 7) >> 1;
        int half = kk & 1;
        int ln   = n8 * 4 + tgi;
        int fidx = ((ww * 3 + region) * 2 + nt) * 8 + kstep;
        int boff = fidx * 256 + ln * 8 + reg * 4 + half * 2;
        *(unsigned short*)(smemS + SB_HI + boff) = __bfloat16_as_ushort(h16);
        *(unsigned short*)(smemS + SB_LO + boff) = __bfloat16_as_ushort(l16);
    }
    for (int i = tid; i < 32 * H_; i += 256) {
        int row = i >> 7, k = i & 127;
        float hv = h0[(size_t)b0 * H_ + i];
        __nv_bfloat16 h16 = __float2bfloat16(hv);
        float lof = hv - __bfloat162float(h16);
        *(unsigned short*)(smemS + SH_HI + row * 272 + k * 2) = __bfloat16_as_ushort(h16);
        *(unsigned short*)(smemS + SH_LO + row * 272 + k * 2) =
            __bfloat16_as_ushort(__float2bfloat16(lof));
    }
    for (int i = tid; i < G_; i += 256) {
        sWyf[i] = W_ih[(size_t)i * (D_ + 1) + D_];
        sBhf[i] = b_hh[i];
    }
    for (int i = tid; i < H_; i += 256) sWof[i] = Wo[i];
    if (tid < 32) sYf[tid] = y0[b0 + tid];
    const float bo_v = bo[0];
    __syncthreads();

    const int colb0 = w * 16 + 2 * tg;

    // ---- load B-hi fragments into persistent registers (once) ----
    uint2 bhiR[3][2][8];
    #pragma unroll
    for (int region = 0; region < 3; region++)
        #pragma unroll
        for (int nt = 0; nt < 2; nt++)
            #pragma unroll
            for (int ks = 0; ks < 8; ks++) {
                int fb = (((w * 3 + region) * 2 + nt) * 8 + ks) * 256 + lane * 8;
                bhiR[region][nt][ks] = *(const uint2*)(smemS + SB_HI + fb);
            }

    for (int t = 0; t < T_; t++) {
        const float* gx = g_gx + ((size_t)t * B_ + b0) * G_;

        // gx prefetch (consumed in epilogue): [region][mt][rr][nt]
        float2 xg[3][2][2][2];
        #pragma unroll
        for (int region = 0; region < 3; region++)
            #pragma unroll
            for (int mt = 0; mt < 2; mt++)
                #pragma unroll
                for (int rr = 0; rr < 2; rr++)
                    #pragma unroll
                    for (int nt = 0; nt < 2; nt++) {
                        int row = mt * 16 + rr * 8 + g;
                        xg[region][mt][rr][nt] = *(const float2*)(
                            gx + (size_t)row * G_ + region * 128 + colb0 + nt * 8);
                    }

        float c[2][3][2][4];
        #pragma unroll
        for (int mt = 0; mt < 2; mt++)
            #pragma unroll
            for (int region = 0; region < 3; region++)
                #pragma unroll
                for (int nt = 0; nt < 2; nt++)
                    #pragma unroll
                    for (int q = 0; q < 4; q++) c[mt][region][nt][q] = 0.f;

        // ------ tensor-core mainloop (3-product, B-hi from registers) ------
        #pragma unroll
        for (int ks = 0; ks < 8; ks++) {
            uint32_t ahi[2][4], alo[2][4];
            #pragma unroll
            for (int mt = 0; mt < 2; mt++) {
                const char* ph = smemS + SH_HI + (mt * 16 + g) * 272 + ks * 32 + tg * 4;
                ahi[mt][0] = *(const uint32_t*)(ph);
                ahi[mt][1] = *(const uint32_t*)(ph + 8 * 272);
                ahi[mt][2] = *(const uint32_t*)(ph + 16);
                ahi[mt][3] = *(const uint32_t*)(ph + 8 * 272 + 16);
                const char* pl = smemS + SH_LO + (mt * 16 + g) * 272 + ks * 32 + tg * 4;
                alo[mt][0] = *(const uint32_t*)(pl);
                alo[mt][1] = *(const uint32_t*)(pl + 8 * 272);
                alo[mt][2] = *(const uint32_t*)(pl + 16);
                alo[mt][3] = *(const uint32_t*)(pl + 8 * 272 + 16);
            }
            #pragma unroll
            for (int region = 0; region < 3; region++)
                #pragma unroll
                for (int nt = 0; nt < 2; nt++) {
                    int fb = (((w * 3 + region) * 2 + nt) * 8 + ks) * 256 + lane * 8;
                    uint2 blo = *(const uint2*)(smemS + SB_LO + fb);
                    uint2 bhi = bhiR[region][nt][ks];
                    #pragma unroll
                    for (int mt = 0; mt < 2; mt++) {
                        MMA_BF16(c[mt][region][nt], ahi[mt], bhi);
                        MMA_BF16(c[mt][region][nt], ahi[mt], blo);
                        MMA_BF16(c[mt][region][nt], alo[mt], bhi);
                    }
                }
        }

        // ------ epilogue: gates + h update ------
        float2 wyc[3][2], bhc[3][2], woc[2];
        #pragma unroll
        for (int region = 0; region < 3; region++)
            #pragma unroll
            for (int nt = 0; nt < 2; nt++) {
                wyc[region][nt] = *(const float2*)(sWyf + region * 128 + colb0 + nt * 8);
                bhc[region][nt] = *(const float2*)(sBhf + region * 128 + colb0 + nt * 8);
            }
        woc[0] = *(const float2*)(sWof + colb0);
        woc[1] = *(const float2*)(sWof + colb0 + 8);

        float pacc[4] = {0.f, 0.f, 0.f, 0.f};
        uint32_t hhiN[2][2][2], hloN[2][2][2];
        #pragma unroll
        for (int mt = 0; mt < 2; mt++)
            #pragma unroll
            for (int rr = 0; rr < 2; rr++) {
                int row = mt * 16 + rr * 8 + g;
                float y = sYf[row];
                #pragma unroll
                for (int nt = 0; nt < 2; nt++) {
                    int cb = (colb0 + nt * 8) * 2;
                    uint32_t hpw = *(const uint32_t*)(smemS + SH_HI + row * 272 + cb);
                    uint32_t lpw = *(const uint32_t*)(smemS + SH_LO + row * 272 + cb);
                    float hp0 = __bfloat162float(__ushort_as_bfloat16((unsigned short)(hpw)))
                              + __bfloat162float(__ushort_as_bfloat16((unsigned short)(lpw)));
                    float hp1 = __bfloat162float(__ushort_as_bfloat16((unsigned short)(hpw >> 16)))
                              + __bfloat162float(__ushort_as_bfloat16((unsigned short)(lpw >> 16)));

                    int i0 = rr * 2;
                    float r0 = fast_sigmoid(xg[0][mt][rr][nt].x + y * wyc[0][nt].x + bhc[0][nt].x + c[mt][0][nt][i0]);
                    float z0 = fast_sigmoid(xg[1][mt][rr][nt].x + y * wyc[1][nt].x + bhc[1][nt].x + c[mt][1][nt][i0]);
                    float n0 = fast_tanh  (xg[2][mt][rr][nt].x + y * wyc[2][nt].x + r0 * (bhc[2][nt].x + c[mt][2][nt][i0]));
                    float h0v = (1.f - z0) * n0 + z0 * hp0;

                    float r1 = fast_sigmoid(xg[0][mt][rr][nt].y + y * wyc[0][nt].y + bhc[0][nt].y + c[mt][0][nt][i0 + 1]);
                    float z1 = fast_sigmoid(xg[1][mt][rr][nt].y + y * wyc[1][nt].y + bhc[1][nt].y + c[mt][1][nt][i0 + 1]);
                    float n1 = fast_tanh  (xg[2][mt][rr][nt].y + y * wyc[2][nt].y + r1 * (bhc[2][nt].y + c[mt][2][nt][i0 + 1]));
                    float h1v = (1.f - z1) * n1 + z1 * hp1;

                    pacc[mt * 2 + rr] += h0v * woc[nt].x + h1v * woc[nt].y;

                    __nv_bfloat16 hb0 = __float2bfloat16(h0v);
                    __nv_bfloat16 hb1 = __float2bfloat16(h1v);
                    float l0 = h0v - __bfloat162float(hb0);
                    float l1 = h1v - __bfloat162float(hb1);
                    hhiN[mt][rr][nt] = (uint32_t)__bfloat16_as_ushort(hb0)
                                     | ((uint32_t)__bfloat16_as_ushort(hb1) << 16);
                    hloN[mt][rr][nt] = (uint32_t)__bfloat16_as_ushort(__float2bfloat16(l0))
                                     | ((uint32_t)__bfloat16_as_ushort(__float2bfloat16(l1)) << 16);
                }
            }
        __syncthreads();

        #pragma unroll
        for (int mt = 0; mt < 2; mt++)
            #pragma unroll
            for (int rr = 0; rr < 2; rr++) {
                int row = mt * 16 + rr * 8 + g;
                #pragma unroll
                for (int nt = 0; nt < 2; nt++) {
                    int cb = (colb0 + nt * 8) * 2;
                    *(uint32_t*)(smemS + SH_HI + row * 272 + cb) = hhiN[mt][rr][nt];
                    *(uint32_t*)(smemS + SH_LO + row * 272 + cb) = hloN[mt][rr][nt];
                }
            }

        #pragma unroll
        for (int i = 0; i < 4; i++) {
            pacc[i] += __shfl_xor_sync(0xffffffffu, pacc[i], 1);
            pacc[i] += __shfl_xor_sync(0xffffffffu, pacc[i], 2);
        }
        if (tg == 0) {
            sRf[w * 32 + g]      = pacc[0];
            sRf[w * 32 + g + 8]  = pacc[1];
            sRf[w * 32 + g + 16] = pacc[2];
            sRf[w * 32 + g + 24] = pacc[3];
        }
        __syncthreads();
        if (tid < 32) {
            float s = bo_v;
            #pragma unroll
            for (int ww = 0; ww < 8; ww++) s += sRf[ww * 32 + tid];
            sYf[tid] = s;
            out[(size_t)(b0 + tid) * T_ + t] = s;
        }
        __syncthreads();
    }
}

// ---------------------------------------------------------------------------
extern "C" void kernel_launch(void* const* d_in, const int* in_sizes, int n_in,
                              void* d_out, int out_size)
{
    const float* feats = (const float*)d_in[0];
    const float* h0    = (const float*)d_in[1];
    const float* y0    = (const float*)d_in[2];
    const float* W_ih  = (const float*)d_in[3];
    const float* W_hh  = (const float*)d_in[4];
    const float* b_ih  = (const float*)d_in[5];
    const float* b_hh  = (const float*)d_in[6];
    const float* Wo    = (const float*)d_in[7];
    const float* bo    = (const float*)d_in[8];
    float* out = (float*)d_out;

    cudaFuncSetAttribute(gx_kernel, cudaFuncAttributeMaxDynamicSharedMemorySize, G_TOT);
    gx_kernel<<<148, 256, G_TOT>>>(feats, W_ih, b_ih);

    cudaFuncSetAttribute(scan_kernel, cudaFuncAttributeMaxDynamicSharedMemorySize, S_TOT);
    scan_kernel<<<B_ / 32, 256, S_TOT>>>(h0, y0, W_ih, W_hh, b_hh, Wo, bo, out);
}

// round 15
// speedup vs baseline: 2.2560x; 1.0264x over previous
#include <cuda_runtime.h>
#include <cuda_bf16.h>
#include <cstdint>
#include <cstddef>

#define B_ 4096
#define T_ 168
#define D_ 64
#define H_ 128
#define G_ 384   // 3*H

// ---------------------------------------------------------------------------
// helpers
// ---------------------------------------------------------------------------
__device__ __forceinline__ float tanh_hw(float x) {
    float r;
    asm("tanh.approx.f32 %0, %1;" : "=f"(r) : "f"(x));
    return r;
}
__device__ __forceinline__ float fast_sigmoid(float x) {
    return fmaf(0.5f, tanh_hw(0.5f * x), 0.5f);   // 1 MUFU + 2 fma-pipe ops
}
__device__ __forceinline__ float fast_tanh(float x) {
    return tanh_hw(x);                            // 1 MUFU
}

// warp-level bf16 tensor-core mma (HMMA path, plain sm_100-legal PTX)
#define MMA_BF16(c, a, b) \
    asm volatile("mma.sync.aligned.m16n8k16.row.col.f32.bf16.bf16.f32 " \
        "{%0,%1,%2,%3}, {%4,%5,%6,%7}, {%8,%9}, {%0,%1,%2,%3};" \
        : "+f"((c)[0]), "+f"((c)[1]), "+f"((c)[2]), "+f"((c)[3]) \
        : "r"((a)[0]), "r"((a)[1]), "r"((a)[2]), "r"((a)[3]), \
          "r"((b).x), "r"((b).y))

// Scratch: gx[t][b][g] fp32, ~1.01 GB device global.
__device__ float g_gx[(size_t)T_ * B_ * G_];

// ---------------------------------------------------------------------------
// Kernel A (R14 measured, ~0.46 ms): mma.sync bf16, 3-product split,
// pad-144 A image. Unchanged.
// ---------------------------------------------------------------------------
#define GB_HI  0                      // W_ih hi fragments (49152 B)
#define GB_LO  49152                  // W_ih lo fragments (49152 B)
#define GA_HI  98304                  // feats hi image 128 x 144 B
#define GA_LO  (98304 + 18432)
#define GBIAS  (98304 + 36864)        // 384 f32
#define G_TOT  (GBIAS + 1536)

__global__ void __launch_bounds__(256, 1)
gx_kernel(const float* __restrict__ feats, const float* __restrict__ W_ih,
          const float* __restrict__ b_ih)
{
    extern __shared__ char smemA[];
    const int tid  = threadIdx.x;
    const int w    = tid >> 5;
    const int lane = tid & 31;
    const int g    = lane >> 2;
    const int tg   = lane & 3;

    float* sBias = (float*)(smemA + GBIAS);

    for (int idx = tid; idx < G_ * D_; idx += 256) {
        int n = idx >> 6;
        int k = idx & 63;
        float wv = W_ih[(size_t)n * (D_ + 1) + k];
        __nv_bfloat16 h16 = __float2bfloat16(wv);
        float lof = wv - __bfloat162float(h16);
        __nv_bfloat16 l16 = __float2bfloat16(lof);
        int region = n >> 7, off = n & 127;
        int ww = off >> 4, nt = (off >> 3) & 1, n8 = off & 7;
        int kstep = k >> 4, kk = k & 15;
        int reg  = kk >> 3;
        int tgi  = (kk & 7) >> 1;
        int half = kk & 1;
        int ln   = n8 * 4 + tgi;
        int fidx = ((ww * 3 + region) * 2 + nt) * 4 + kstep;
        int boff = fidx * 256 + ln * 8 + reg * 4 + half * 2;
        *(unsigned short*)(smemA + GB_HI + boff) = __bfloat16_as_ushort(h16);
        *(unsigned short*)(smemA + GB_LO + boff) = __bfloat16_as_ushort(l16);
    }
    for (int i = tid; i < G_; i += 256) sBias[i] = b_ih[i];
    __syncthreads();

    const int NTILES = (B_ * T_) / 128;    // 5376
    const int colb0  = w * 16 + 2 * tg;
    const int lrow   = tid >> 1;
    const int lhalf  = tid & 1;

    float2 fv[16];
    {
        int t0 = blockIdx.x >> 5, bb0 = (blockIdx.x & 31) * 128;
        const float* src = feats + ((size_t)(bb0 + lrow) * T_ + t0) * D_ + lhalf * 32;
        #pragma unroll
        for (int i = 0; i < 16; i++) fv[i] = *(const float2*)(src + 2 * i);
    }

    for (int til = blockIdx.x; til < NTILES; til += 148) {
        const int t  = til >> 5;
        const int bb = (til & 31) * 128;

        #pragma unroll
        for (int i = 0; i < 16; i++) {
            __nv_bfloat162 hh = __floats2bfloat162_rn(fv[i].x, fv[i].y);
            float l0 = fv[i].x - __bfloat162float(__low2bfloat16(hh));
            float l1 = fv[i].y - __bfloat162float(__high2bfloat16(hh));
            __nv_bfloat162 ll = __floats2bfloat162_rn(l0, l1);
            int boff = lrow * 144 + lhalf * 64 + i * 4;
            *(uint32_t*)(smemA + GA_HI + boff) = *(uint32_t*)&hh;
            *(uint32_t*)(smemA + GA_LO + boff) = *(uint32_t*)&ll;
        }
        __syncthreads();

        int tn = til + 148;
        if (tn < NTILES) {
            int t1 = tn >> 5, b1 = (tn & 31) * 128;
            const float* src = feats + ((size_t)(b1 + lrow) * T_ + t1) * D_ + lhalf * 32;
            #pragma unroll
            for (int i = 0; i < 16; i++) fv[i] = *(const float2*)(src + 2 * i);
        }

        #pragma unroll 1
        for (int mt = 0; mt < 8; mt++) {
            float c[3][2][4];
            #pragma unroll
            for (int r = 0; r < 3; r++)
                #pragma unroll
                for (int nt = 0; nt < 2; nt++)
                    #pragma unroll
                    for (int q = 0; q < 4; q++) c[r][nt][q] = 0.f;

            #pragma unroll
            for (int ks = 0; ks < 4; ks++) {
                uint32_t ahi[4], alo[4];
                const char* ph = smemA + GA_HI + (mt * 16 + g) * 144 + ks * 32 + tg * 4;
                ahi[0] = *(const uint32_t*)(ph);
                ahi[1] = *(const uint32_t*)(ph + 8 * 144);
                ahi[2] = *(const uint32_t*)(ph + 16);
                ahi[3] = *(const uint32_t*)(ph + 8 * 144 + 16);
                const char* pl = smemA + GA_LO + (mt * 16 + g) * 144 + ks * 32 + tg * 4;
                alo[0] = *(const uint32_t*)(pl);
                alo[1] = *(const uint32_t*)(pl + 8 * 144);
                alo[2] = *(const uint32_t*)(pl + 16);
                alo[3] = *(const uint32_t*)(pl + 8 * 144 + 16);

                #pragma unroll
                for (int r = 0; r < 3; r++)
                    #pragma unroll
                    for (int nt = 0; nt < 2; nt++) {
                        int fb = (((w * 3 + r) * 2 + nt) * 4 + ks) * 256 + lane * 8;
                        uint2 bhi = *(const uint2*)(smemA + GB_HI + fb);
                        uint2 blo = *(const uint2*)(smemA + GB_LO + fb);
                        MMA_BF16(c[r][nt], ahi, bhi);
                        MMA_BF16(c[r][nt], ahi, blo);
                        MMA_BF16(c[r][nt], alo, bhi);
                    }
            }

            int row0 = bb + mt * 16 + g;
            #pragma unroll
            for (int r = 0; r < 3; r++)
                #pragma unroll
                for (int nt = 0; nt < 2; nt++) {
                    int col = r * 128 + colb0 + nt * 8;
                    float2 b2 = *(const float2*)(sBias + col);
                    float2 o0 = make_float2(c[r][nt][0] + b2.x, c[r][nt][1] + b2.y);
                    float2 o1 = make_float2(c[r][nt][2] + b2.x, c[r][nt][3] + b2.y);
                    *(float2*)(&g_gx[((size_t)t * B_ + row0) * G_ + col])     = o0;
                    *(float2*)(&g_gx[((size_t)t * B_ + row0 + 8) * G_ + col]) = o1;
                }
        }
        __syncthreads();
    }
}

// ---------------------------------------------------------------------------
// Kernel B: GRU scan, mma.sync bf16, 256 threads, 3-product split,
// B-hi persistent in registers, pad-272 h images. This round:
//   - hw tanh.approx for all activations (halves MUFU pressure)
//   - 2 barriers/step (was 3) + no serialized y-tail: y partials in sRed,
//     summed redundantly per-thread in the NEXT step's epilogue;
//     out[t-1] stored during step t by (w==0, tg==0) threads.
// ---------------------------------------------------------------------------
#define SB_HI  0          // W_hh hi fragments (staging for reg load)
#define SB_LO  98304      // W_hh lo fragments
#define SH_HI  196608     // h hi image, 32 rows x 272 B
#define SH_LO  205312     // h lo image
#define SWY    214016     // wy fp32 [384]
#define SBH    215552     // b_hh fp32 [384]
#define SWO    217088     // Wo fp32 [128]
#define SRED   217600     // 8 x 32 fp32
#define S_TOT  218624

__global__ void __launch_bounds__(256, 1)
scan_kernel(const float* __restrict__ h0, const float* __restrict__ y0,
            const float* __restrict__ W_ih, const float* __restrict__ W_hh,
            const float* __restrict__ b_hh, const float* __restrict__ Wo,
            const float* __restrict__ bo, float* __restrict__ out)
{
    extern __shared__ char smemS[];
    const int tid  = threadIdx.x;
    const int w    = tid >> 5;          // warp 0..7 (column group)
    const int lane = tid & 31;
    const int g    = lane >> 2;         // 0..7
    const int tg   = lane & 3;          // 0..3
    const int b0   = blockIdx.x * 32;

    float* sWyf = (float*)(smemS + SWY);
    float* sBhf = (float*)(smemS + SBH);
    float* sWof = (float*)(smemS + SWO);
    float* sRf  = (float*)(smemS + SRED);

    // ---- init: W_hh -> bf16 hi/lo fragments ----
    for (int idx = tid; idx < G_ * H_; idx += 256) {
        int n = idx >> 7;
        int k = idx & 127;
        float wv = W_hh[idx];
        __nv_bfloat16 h16 = __float2bfloat16(wv);
        float lof = wv - __bfloat162float(h16);
        __nv_bfloat16 l16 = __float2bfloat16(lof);
        int region = n >> 7, off = n & 127;
        int ww = off >> 4, nt = (off >> 3) & 1, n8 = off & 7;
        int kstep = k >> 4, kk = k & 15;
        int reg  = kk >> 3;
        int tgi  = (kk & 7) >> 1;
        int half = kk & 1;
        int ln   = n8 * 4 + tgi;
        int fidx = ((ww * 3 + region) * 2 + nt) * 8 + kstep;
        int boff = fidx * 256 + ln * 8 + reg * 4 + half * 2;
        *(unsigned short*)(smemS + SB_HI + boff) = __bfloat16_as_ushort(h16);
        *(unsigned short*)(smemS + SB_LO + boff) = __bfloat16_as_ushort(l16);
    }
    for (int i = tid; i < 32 * H_; i += 256) {
        int row = i >> 7, k = i & 127;
        float hv = h0[(size_t)b0 * H_ + i];
        __nv_bfloat16 h16 = __float2bfloat16(hv);
        float lof = hv - __bfloat162float(h16);
        *(unsigned short*)(smemS + SH_HI + row * 272 + k * 2) = __bfloat16_as_ushort(h16);
        *(unsigned short*)(smemS + SH_LO + row * 272 + k * 2) =
            __bfloat16_as_ushort(__float2bfloat16(lof));
    }
    for (int i = tid; i < G_; i += 256) {
        sWyf[i] = W_ih[(size_t)i * (D_ + 1) + D_];
        sBhf[i] = b_hh[i];
    }
    for (int i = tid; i < H_; i += 256) sWof[i] = Wo[i];
    // sRed init: slice 0 = y0, slices 1..7 = 0 -> first ysum == y0
    for (int i = tid; i < 8 * 32; i += 256)
        sRf[i] = (i < 32) ? y0[b0 + i] : 0.f;
    const float bo_v = bo[0];
    __syncthreads();

    const int colb0 = w * 16 + 2 * tg;

    // ---- load B-hi fragments into persistent registers (once) ----
    uint2 bhiR[3][2][8];
    #pragma unroll
    for (int region = 0; region < 3; region++)
        #pragma unroll
        for (int nt = 0; nt < 2; nt++)
            #pragma unroll
            for (int ks = 0; ks < 8; ks++) {
                int fb = (((w * 3 + region) * 2 + nt) * 8 + ks) * 256 + lane * 8;
                bhiR[region][nt][ks] = *(const uint2*)(smemS + SB_HI + fb);
            }

    for (int t = 0; t < T_; t++) {
        const float* gx = g_gx + ((size_t)t * B_ + b0) * G_;

        // gx prefetch (consumed in epilogue): [region][mt][rr][nt]
        float2 xg[3][2][2][2];
        #pragma unroll
        for (int region = 0; region < 3; region++)
            #pragma unroll
            for (int mt = 0; mt < 2; mt++)
                #pragma unroll
                for (int rr = 0; rr < 2; rr++)
                    #pragma unroll
                    for (int nt = 0; nt < 2; nt++) {
                        int row = mt * 16 + rr * 8 + g;
                        xg[region][mt][rr][nt] = *(const float2*)(
                            gx + (size_t)row * G_ + region * 128 + colb0 + nt * 8);
                    }

        float c[2][3][2][4];
        #pragma unroll
        for (int mt = 0; mt < 2; mt++)
            #pragma unroll
            for (int region = 0; region < 3; region++)
                #pragma unroll
                for (int nt = 0; nt < 2; nt++)
                    #pragma unroll
                    for (int q = 0; q < 4; q++) c[mt][region][nt][q] = 0.f;

        // ------ tensor-core mainloop (3-product, B-hi from registers) ------
        #pragma unroll
        for (int ks = 0; ks < 8; ks++) {
            uint32_t ahi[2][4], alo[2][4];
            #pragma unroll
            for (int mt = 0; mt < 2; mt++) {
                const char* ph = smemS + SH_HI + (mt * 16 + g) * 272 + ks * 32 + tg * 4;
                ahi[mt][0] = *(const uint32_t*)(ph);
                ahi[mt][1] = *(const uint32_t*)(ph + 8 * 272);
                ahi[mt][2] = *(const uint32_t*)(ph + 16);
                ahi[mt][3] = *(const uint32_t*)(ph + 8 * 272 + 16);
                const char* pl = smemS + SH_LO + (mt * 16 + g) * 272 + ks * 32 + tg * 4;
                alo[mt][0] = *(const uint32_t*)(pl);
                alo[mt][1] = *(const uint32_t*)(pl + 8 * 272);
                alo[mt][2] = *(const uint32_t*)(pl + 16);
                alo[mt][3] = *(const uint32_t*)(pl + 8 * 272 + 16);
            }
            #pragma unroll
            for (int region = 0; region < 3; region++)
                #pragma unroll
                for (int nt = 0; nt < 2; nt++) {
                    int fb = (((w * 3 + region) * 2 + nt) * 8 + ks) * 256 + lane * 8;
                    uint2 blo = *(const uint2*)(smemS + SB_LO + fb);
                    uint2 bhi = bhiR[region][nt][ks];
                    #pragma unroll
                    for (int mt = 0; mt < 2; mt++) {
                        MMA_BF16(c[mt][region][nt], ahi[mt], bhi);
                        MMA_BF16(c[mt][region][nt], ahi[mt], blo);
                        MMA_BF16(c[mt][region][nt], alo[mt], bhi);
                    }
                }
        }

        // ------ epilogue ------
        float2 wyc[3][2], bhc[3][2], woc[2];
        #pragma unroll
        for (int region = 0; region < 3; region++)
            #pragma unroll
            for (int nt = 0; nt < 2; nt++) {
                wyc[region][nt] = *(const float2*)(sWyf + region * 128 + colb0 + nt * 8);
                bhc[region][nt] = *(const float2*)(sBhf + region * 128 + colb0 + nt * 8);
            }
        woc[0] = *(const float2*)(sWof + colb0);
        woc[1] = *(const float2*)(sWof + colb0 + 8);

        float pacc[4] = {0.f, 0.f, 0.f, 0.f};
        uint32_t hhiN[2][2][2], hloN[2][2][2];
        #pragma unroll
        for (int mt = 0; mt < 2; mt++)
            #pragma unroll
            for (int rr = 0; rr < 2; rr++) {
                int row = mt * 16 + rr * 8 + g;
                // y_prev: redundant per-thread sum of the 8 warp slices
                float y = sRf[row] + sRf[32 + row] + sRf[64 + row] + sRf[96 + row]
                        + sRf[128 + row] + sRf[160 + row] + sRf[192 + row] + sRf[224 + row];
                if (t > 0 && w == 0 && tg == 0)
                    out[(size_t)(b0 + row) * T_ + (t - 1)] = y;
                #pragma unroll
                for (int nt = 0; nt < 2; nt++) {
                    int cb = (colb0 + nt * 8) * 2;
                    uint32_t hpw = *(const uint32_t*)(smemS + SH_HI + row * 272 + cb);
                    uint32_t lpw = *(const uint32_t*)(smemS + SH_LO + row * 272 + cb);
                    float hp0 = __bfloat162float(__ushort_as_bfloat16((unsigned short)(hpw)))
                              + __bfloat162float(__ushort_as_bfloat16((unsigned short)(lpw)));
                    float hp1 = __bfloat162float(__ushort_as_bfloat16((unsigned short)(hpw >> 16)))
                              + __bfloat162float(__ushort_as_bfloat16((unsigned short)(lpw >> 16)));

                    int i0 = rr * 2;
                    float r0 = fast_sigmoid(xg[0][mt][rr][nt].x + y * wyc[0][nt].x + bhc[0][nt].x + c[mt][0][nt][i0]);
                    float z0 = fast_sigmoid(xg[1][mt][rr][nt].x + y * wyc[1][nt].x + bhc[1][nt].x + c[mt][1][nt][i0]);
                    float n0 = fast_tanh  (xg[2][mt][rr][nt].x + y * wyc[2][nt].x + r0 * (bhc[2][nt].x + c[mt][2][nt][i0]));
                    float h0v = (1.f - z0) * n0 + z0 * hp0;

                    float r1 = fast_sigmoid(xg[0][mt][rr][nt].y + y * wyc[0][nt].y + bhc[0][nt].y + c[mt][0][nt][i0 + 1]);
                    float z1 = fast_sigmoid(xg[1][mt][rr][nt].y + y * wyc[1][nt].y + bhc[1][nt].y + c[mt][1][nt][i0 + 1]);
                    float n1 = fast_tanh  (xg[2][mt][rr][nt].y + y * wyc[2][nt].y + r1 * (bhc[2][nt].y + c[mt][2][nt][i0 + 1]));
                    float h1v = (1.f - z1) * n1 + z1 * hp1;

                    pacc[mt * 2 + rr] += h0v * woc[nt].x + h1v * woc[nt].y;

                    __nv_bfloat16 hb0 = __float2bfloat16(h0v);
                    __nv_bfloat16 hb1 = __float2bfloat16(h1v);
                    float l0 = h0v - __bfloat162float(hb0);
                    float l1 = h1v - __bfloat162float(hb1);
                    hhiN[mt][rr][nt] = (uint32_t)__bfloat16_as_ushort(hb0)
                                     | ((uint32_t)__bfloat16_as_ushort(hb1) << 16);
                    hloN[mt][rr][nt] = (uint32_t)__bfloat16_as_ushort(__float2bfloat16(l0))
                                     | ((uint32_t)__bfloat16_as_ushort(__float2bfloat16(l1)) << 16);
                }
            }
        __syncthreads();   // all reads of sH and sRed done

        #pragma unroll
        for (int mt = 0; mt < 2; mt++)
            #pragma unroll
            for (int rr = 0; rr < 2; rr++) {
                int row = mt * 16 + rr * 8 + g;
                #pragma unroll
                for (int nt = 0; nt < 2; nt++) {
                    int cb = (colb0 + nt * 8) * 2;
                    *(uint32_t*)(smemS + SH_HI + row * 272 + cb) = hhiN[mt][rr][nt];
                    *(uint32_t*)(smemS + SH_LO + row * 272 + cb) = hloN[mt][rr][nt];
                }
            }
        // y partials: fold tg lanes, slice w gets this warp's contribution
        #pragma unroll
        for (int i = 0; i < 4; i++) {
            pacc[i] += __shfl_xor_sync(0xffffffffu, pacc[i], 1);
            pacc[i] += __shfl_xor_sync(0xffffffffu, pacc[i], 2);
        }
        if (tg == 0) {
            float b_add = (w == 0) ? bo_v : 0.f;
            sRf[w * 32 + g]      = pacc[0] + b_add;
            sRf[w * 32 + g + 8]  = pacc[1] + b_add;
            sRf[w * 32 + g + 16] = pacc[2] + b_add;
            sRf[w * 32 + g + 24] = pacc[3] + b_add;
        }
        __syncthreads();   // h + partials visible for next step
    }

    // flush final step's y (partials written in last epilogue)
    if (w == 0 && tg == 0) {
        #pragma unroll
        for (int q = 0; q < 4; q++) {
            int row = q * 8 + g;
            float y = sRf[row] + sRf[32 + row] + sRf[64 + row] + sRf[96 + row]
                    + sRf[128 + row] + sRf[160 + row] + sRf[192 + row] + sRf[224 + row];
            out[(size_t)(b0 + row) * T_ + (T_ - 1)] = y;
        }
    }
}

// ---------------------------------------------------------------------------
extern "C" void kernel_launch(void* const* d_in, const int* in_sizes, int n_in,
                              void* d_out, int out_size)
{
    const float* feats = (const float*)d_in[0];
    const float* h0    = (const float*)d_in[1];
    const float* y0    = (const float*)d_in[2];
    const float* W_ih  = (const float*)d_in[3];
    const float* W_hh  = (const float*)d_in[4];
    const float* b_ih  = (const float*)d_in[5];
    const float* b_hh  = (const float*)d_in[6];
    const float* Wo    = (const float*)d_in[7];
    const float* bo    = (const float*)d_in[8];
    float* out = (float*)d_out;

    cudaFuncSetAttribute(gx_kernel, cudaFuncAttributeMaxDynamicSharedMemorySize, G_TOT);
    gx_kernel<<<148, 256, G_TOT>>>(feats, W_ih, b_ih);

    cudaFuncSetAttribute(scan_kernel, cudaFuncAttributeMaxDynamicSharedMemorySize, S_TOT);
    scan_kernel<<<B_ / 32, 256, S_TOT>>>(h0, y0, W_ih, W_hh, b_hh, Wo, bo, out);
}

// round 16
// speedup vs baseline: 3.3423x; 1.4815x over previous
#include <cuda_runtime.h>
#include <cuda_bf16.h>
#include <cstdint>
#include <cstddef>

#define B_ 4096
#define T_ 168
#define D_ 64
#define H_ 128
#define G_ 384   // 3*H

// ---------------------------------------------------------------------------
// helpers
// ---------------------------------------------------------------------------
__device__ __forceinline__ float tanh_hw(float x) {
    float r;
    asm("tanh.approx.f32 %0, %1;" : "=f"(r) : "f"(x));
    return r;
}
__device__ __forceinline__ float fast_sigmoid(float x) {
    return fmaf(0.5f, tanh_hw(0.5f * x), 0.5f);
}

// warp-level bf16 tensor-core mma (HMMA path, plain sm_100-legal PTX)
#define MMA_BF16(c, a, b) \
    asm volatile("mma.sync.aligned.m16n8k16.row.col.f32.bf16.bf16.f32 " \
        "{%0,%1,%2,%3}, {%4,%5,%6,%7}, {%8,%9}, {%0,%1,%2,%3};" \
        : "+f"((c)[0]), "+f"((c)[1]), "+f"((c)[2]), "+f"((c)[3]) \
        : "r"((a)[0]), "r"((a)[1]), "r"((a)[2]), "r"((a)[3]), \
          "r"((b).x), "r"((b).y))

// ---------------------------------------------------------------------------
// FUSED kernel: GRU scan with gx computed in-step on tensor cores.
// 128 blocks x 256 threads (8 warps), 32 batch rows per block.
// Per step t:
//   accum  = x_t @ W_ih^T (4 ks)  +  h @ W_hh^T (8 ks), bf16 3-product split.
//   n-region x-part kept in separate accumulators (b_hh+gh sits inside r*()).
// W_hh-hi fragments persistent in registers; W_hh-lo + W_ih hi/lo in smem.
// feats for t+1 LDG'd at step top (regs), converted to bf16 images in the
// store phase. 2 barriers/step; y via sRed slices (R15 scheme).
// ---------------------------------------------------------------------------
#define SWLO   0          // W_hh-lo fragments (98304 B)
#define SWIH   98304      // W_ih-hi fragments (49152)   [init: W_hh-hi staging]
#define SWIL   147456     // W_ih-lo fragments (49152)
#define SH_HI  196608     // h hi image, 32 x 272 B
#define SH_LO  205312     // h lo image
#define SX_HI  214016     // feats hi image, 32 x 144 B
#define SX_LO  218624     // feats lo image
#define SWY    223232     // wy fp32 [384]
#define SBRZ   224768     // b_ih+b_hh, gates 0..255 (r,z regions)
#define SBIN   225792     // b_ih, n region [128]
#define SBHN   226304     // b_hh, n region [128]
#define SWO    226816     // Wo [128]
#define SRED   227328     // 8 x 32 fp32
#define S_TOT  228352

__global__ void __launch_bounds__(256, 1)
fused_kernel(const float* __restrict__ feats, const float* __restrict__ h0,
             const float* __restrict__ y0, const float* __restrict__ W_ih,
             const float* __restrict__ W_hh, const float* __restrict__ b_ih,
             const float* __restrict__ b_hh, const float* __restrict__ Wo,
             const float* __restrict__ bo, float* __restrict__ out)
{
    extern __shared__ char smemS[];
    const int tid  = threadIdx.x;
    const int w    = tid >> 5;          // warp 0..7 (column group)
    const int lane = tid & 31;
    const int g    = lane >> 2;         // 0..7
    const int tg   = lane & 3;          // 0..3
    const int b0   = blockIdx.x * 32;

    float* sWyf  = (float*)(smemS + SWY);
    float* sBrzf = (float*)(smemS + SBRZ);
    float* sBinf = (float*)(smemS + SBIN);
    float* sBhnf = (float*)(smemS + SBHN);
    float* sWof  = (float*)(smemS + SWO);
    float* sRf   = (float*)(smemS + SRED);

    // ---- init: W_hh -> lo frags at SWLO (permanent), hi frags staged at SWIH ----
    for (int idx = tid; idx < G_ * H_; idx += 256) {
        int n = idx >> 7;
        int k = idx & 127;
        float wv = W_hh[idx];
        __nv_bfloat16 h16 = __float2bfloat16(wv);
        float lof = wv - __bfloat162float(h16);
        __nv_bfloat16 l16 = __float2bfloat16(lof);
        int region = n >> 7, off = n & 127;
        int ww = off >> 4, nt = (off >> 3) & 1, n8 = off & 7;
        int kstep = k >> 4, kk = k & 15;
        int reg  = kk >> 3;
        int tgi  = (kk & 7) >> 1;
        int half = kk & 1;
        int ln   = n8 * 4 + tgi;
        int fidx = ((ww * 3 + region) * 2 + nt) * 8 + kstep;
        int boff = fidx * 256 + ln * 8 + reg * 4 + half * 2;
        *(unsigned short*)(smemS + SWLO + boff) = __bfloat16_as_ushort(l16);
        *(unsigned short*)(smemS + SWIH + boff) = __bfloat16_as_ushort(h16);  // staging
    }
    // h0 images (pad 272: conflict-free frag loads)
    for (int i = tid; i < 32 * H_; i += 256) {
        int row = i >> 7, k = i & 127;
        float hv = h0[(size_t)b0 * H_ + i];
        __nv_bfloat16 h16 = __float2bfloat16(hv);
        float lof = hv - __bfloat162float(h16);
        *(unsigned short*)(smemS + SH_HI + row * 272 + k * 2) = __bfloat16_as_ushort(h16);
        *(unsigned short*)(smemS + SH_LO + row * 272 + k * 2) =
            __bfloat16_as_ushort(__float2bfloat16(lof));
    }
    for (int i = tid; i < G_; i += 256)
        sWyf[i] = W_ih[(size_t)i * (D_ + 1) + D_];
    for (int i = tid; i < 2 * H_; i += 256)
        sBrzf[i] = b_ih[i] + b_hh[i];
    for (int i = tid; i < H_; i += 256) {
        sBinf[i] = b_ih[2 * H_ + i];
        sBhnf[i] = b_hh[2 * H_ + i];
        sWof[i]  = Wo[i];
    }
    for (int i = tid; i < 8 * 32; i += 256)
        sRf[i] = (i < 32) ? y0[b0 + i] : 0.f;
    const float bo_v = bo[0];
    __syncthreads();

    const int colb0 = w * 16 + 2 * tg;

    // ---- W_hh-hi fragments -> persistent registers ----
    uint2 bhiR[3][2][8];
    #pragma unroll
    for (int region = 0; region < 3; region++)
        #pragma unroll
        for (int nt = 0; nt < 2; nt++)
            #pragma unroll
            for (int ks = 0; ks < 8; ks++) {
                int fb = (((w * 3 + region) * 2 + nt) * 8 + ks) * 256 + lane * 8;
                bhiR[region][nt][ks] = *(const uint2*)(smemS + SWIH + fb);
            }
    __syncthreads();

    // ---- overwrite staging with W_ih hi/lo fragments (4-kstep layout) ----
    for (int idx = tid; idx < G_ * D_; idx += 256) {
        int n = idx >> 6;
        int k = idx & 63;
        float wv = W_ih[(size_t)n * (D_ + 1) + k];
        __nv_bfloat16 h16 = __float2bfloat16(wv);
        float lof = wv - __bfloat162float(h16);
        __nv_bfloat16 l16 = __float2bfloat16(lof);
        int region = n >> 7, off = n & 127;
        int ww = off >> 4, nt = (off >> 3) & 1, n8 = off & 7;
        int kstep = k >> 4, kk = k & 15;
        int reg  = kk >> 3;
        int tgi  = (kk & 7) >> 1;
        int half = kk & 1;
        int ln   = n8 * 4 + tgi;
        int fidx = ((ww * 3 + region) * 2 + nt) * 4 + kstep;
        int boff = fidx * 256 + ln * 8 + reg * 4 + half * 2;
        *(unsigned short*)(smemS + SWIH + boff) = __bfloat16_as_ushort(h16);
        *(unsigned short*)(smemS + SWIL + boff) = __bfloat16_as_ushort(l16);
    }
    // feats image for t = 0
    {
        int r = tid >> 3, k0 = (tid & 7) * 8;
        const float* fp = feats + ((size_t)(b0 + r) * T_) * D_ + k0;
        float fs[8];
        #pragma unroll
        for (int j = 0; j < 8; j++) fs[j] = fp[j];
        #pragma unroll
        for (int j = 0; j < 4; j++) {
            __nv_bfloat162 hh = __floats2bfloat162_rn(fs[2 * j], fs[2 * j + 1]);
            float l0 = fs[2 * j]     - __bfloat162float(__low2bfloat16(hh));
            float l1 = fs[2 * j + 1] - __bfloat162float(__high2bfloat16(hh));
            __nv_bfloat162 ll = __floats2bfloat162_rn(l0, l1);
            int boff = r * 144 + k0 * 2 + j * 4;
            *(uint32_t*)(smemS + SX_HI + boff) = *(uint32_t*)&hh;
            *(uint32_t*)(smemS + SX_LO + boff) = *(uint32_t*)&ll;
        }
    }
    __syncthreads();

    for (int t = 0; t < T_; t++) {
        // prefetch feats for t+1 into registers
        float4 fA, fB;
        if (t < T_ - 1) {
            const float* fp = feats + ((size_t)(b0 + (tid >> 3)) * T_ + (t + 1)) * D_
                            + (tid & 7) * 8;
            fA = *(const float4*)(fp);
            fB = *(const float4*)(fp + 4);
        }

        float c[2][3][2][4];      // h-part (regions r,z,n) + x-part (r,z)
        float cxn[2][2][4];       // x-part of n region (kept outside r*(.))
        #pragma unroll
        for (int mt = 0; mt < 2; mt++) {
            #pragma unroll
            for (int region = 0; region < 3; region++)
                #pragma unroll
                for (int nt = 0; nt < 2; nt++)
                    #pragma unroll
                    for (int q = 0; q < 4; q++) c[mt][region][nt][q] = 0.f;
            #pragma unroll
            for (int nt = 0; nt < 2; nt++)
                #pragma unroll
                for (int q = 0; q < 4; q++) cxn[mt][nt][q] = 0.f;
        }

        // ------ x-MMAs: x_t @ W_ih^T (4 ks, 3-product) ------
        #pragma unroll
        for (int ks = 0; ks < 4; ks++) {
            uint32_t axh[2][4], axl[2][4];
            #pragma unroll
            for (int mt = 0; mt < 2; mt++) {
                const char* ph = smemS + SX_HI + (mt * 16 + g) * 144 + ks * 32 + tg * 4;
                axh[mt][0] = *(const uint32_t*)(ph);
                axh[mt][1] = *(const uint32_t*)(ph + 8 * 144);
                axh[mt][2] = *(const uint32_t*)(ph + 16);
                axh[mt][3] = *(const uint32_t*)(ph + 8 * 144 + 16);
                const char* pl = smemS + SX_LO + (mt * 16 + g) * 144 + ks * 32 + tg * 4;
                axl[mt][0] = *(const uint32_t*)(pl);
                axl[mt][1] = *(const uint32_t*)(pl + 8 * 144);
                axl[mt][2] = *(const uint32_t*)(pl + 16);
                axl[mt][3] = *(const uint32_t*)(pl + 8 * 144 + 16);
            }
            #pragma unroll
            for (int region = 0; region < 3; region++)
                #pragma unroll
                for (int nt = 0; nt < 2; nt++) {
                    int fb = (((w * 3 + region) * 2 + nt) * 4 + ks) * 256 + lane * 8;
                    uint2 bih_ = *(const uint2*)(smemS + SWIH + fb);
                    uint2 bil_ = *(const uint2*)(smemS + SWIL + fb);
                    #pragma unroll
                    for (int mt = 0; mt < 2; mt++) {
                        float* dst = (region < 2) ? c[mt][region][nt] : cxn[mt][nt];
                        MMA_BF16(dst, axh[mt], bih_);
                        MMA_BF16(dst, axh[mt], bil_);
                        MMA_BF16(dst, axl[mt], bih_);
                    }
                }
        }

        // ------ h-MMAs: h @ W_hh^T (8 ks, 3-product, B-hi from regs) ------
        #pragma unroll
        for (int ks = 0; ks < 8; ks++) {
            uint32_t ahi[2][4], alo[2][4];
            #pragma unroll
            for (int mt = 0; mt < 2; mt++) {
                const char* ph = smemS + SH_HI + (mt * 16 + g) * 272 + ks * 32 + tg * 4;
                ahi[mt][0] = *(const uint32_t*)(ph);
                ahi[mt][1] = *(const uint32_t*)(ph + 8 * 272);
                ahi[mt][2] = *(const uint32_t*)(ph + 16);
                ahi[mt][3] = *(const uint32_t*)(ph + 8 * 272 + 16);
                const char* pl = smemS + SH_LO + (mt * 16 + g) * 272 + ks * 32 + tg * 4;
                alo[mt][0] = *(const uint32_t*)(pl);
                alo[mt][1] = *(const uint32_t*)(pl + 8 * 272);
                alo[mt][2] = *(const uint32_t*)(pl + 16);
                alo[mt][3] = *(const uint32_t*)(pl + 8 * 272 + 16);
            }
            #pragma unroll
            for (int region = 0; region < 3; region++)
                #pragma unroll
                for (int nt = 0; nt < 2; nt++) {
                    int fb = (((w * 3 + region) * 2 + nt) * 8 + ks) * 256 + lane * 8;
                    uint2 blo = *(const uint2*)(smemS + SWLO + fb);
                    uint2 bhi = bhiR[region][nt][ks];
                    #pragma unroll
                    for (int mt = 0; mt < 2; mt++) {
                        MMA_BF16(c[mt][region][nt], ahi[mt], bhi);
                        MMA_BF16(c[mt][region][nt], ahi[mt], blo);
                        MMA_BF16(c[mt][region][nt], alo[mt], bhi);
                    }
                }
        }

        // ------ epilogue ------
        float2 wyc[3][2], brz[2][2], binc[2], bhnc[2], woc[2];
        #pragma unroll
        for (int region = 0; region < 3; region++)
            #pragma unroll
            for (int nt = 0; nt < 2; nt++)
                wyc[region][nt] = *(const float2*)(sWyf + region * 128 + colb0 + nt * 8);
        #pragma unroll
        for (int region = 0; region < 2; region++)
            #pragma unroll
            for (int nt = 0; nt < 2; nt++)
                brz[region][nt] = *(const float2*)(sBrzf + region * 128 + colb0 + nt * 8);
        #pragma unroll
        for (int nt = 0; nt < 2; nt++) {
            binc[nt] = *(const float2*)(sBinf + colb0 + nt * 8);
            bhnc[nt] = *(const float2*)(sBhnf + colb0 + nt * 8);
            woc[nt]  = *(const float2*)(sWof + colb0 + nt * 8);
        }

        float pacc[4] = {0.f, 0.f, 0.f, 0.f};
        uint32_t hhiN[2][2][2], hloN[2][2][2];
        #pragma unroll
        for (int mt = 0; mt < 2; mt++)
            #pragma unroll
            for (int rr = 0; rr < 2; rr++) {
                int row = mt * 16 + rr * 8 + g;
                float y = sRf[row] + sRf[32 + row] + sRf[64 + row] + sRf[96 + row]
                        + sRf[128 + row] + sRf[160 + row] + sRf[192 + row] + sRf[224 + row];
                if (t > 0 && w == 0 && tg == 0)
                    out[(size_t)(b0 + row) * T_ + (t - 1)] = y;
                #pragma unroll
                for (int nt = 0; nt < 2; nt++) {
                    int cb = (colb0 + nt * 8) * 2;
                    uint32_t hpw = *(const uint32_t*)(smemS + SH_HI + row * 272 + cb);
                    uint32_t lpw = *(const uint32_t*)(smemS + SH_LO + row * 272 + cb);
                    float hp0 = __bfloat162float(__ushort_as_bfloat16((unsigned short)(hpw)))
                              + __bfloat162float(__ushort_as_bfloat16((unsigned short)(lpw)));
                    float hp1 = __bfloat162float(__ushort_as_bfloat16((unsigned short)(hpw >> 16)))
                              + __bfloat162float(__ushort_as_bfloat16((unsigned short)(lpw >> 16)));

                    int i0 = rr * 2;
                    float r0 = fast_sigmoid(c[mt][0][nt][i0] + y * wyc[0][nt].x + brz[0][nt].x);
                    float z0 = fast_sigmoid(c[mt][1][nt][i0] + y * wyc[1][nt].x + brz[1][nt].x);
                    float n0 = tanh_hw(cxn[mt][nt][i0] + y * wyc[2][nt].x + binc[nt].x
                                       + r0 * (bhnc[nt].x + c[mt][2][nt][i0]));
                    float h0v = (1.f - z0) * n0 + z0 * hp0;

                    float r1 = fast_sigmoid(c[mt][0][nt][i0 + 1] + y * wyc[0][nt].y + brz[0][nt].y);
                    float z1 = fast_sigmoid(c[mt][1][nt][i0 + 1] + y * wyc[1][nt].y + brz[1][nt].y);
                    float n1 = tanh_hw(cxn[mt][nt][i0 + 1] + y * wyc[2][nt].y + binc[nt].y
                                       + r1 * (bhnc[nt].y + c[mt][2][nt][i0 + 1]));
                    float h1v = (1.f - z1) * n1 + z1 * hp1;

                    pacc[mt * 2 + rr] += h0v * woc[nt].x + h1v * woc[nt].y;

                    __nv_bfloat16 hb0 = __float2bfloat16(h0v);
                    __nv_bfloat16 hb1 = __float2bfloat16(h1v);
                    float l0 = h0v - __bfloat162float(hb0);
                    float l1 = h1v - __bfloat162float(hb1);
                    hhiN[mt][rr][nt] = (uint32_t)__bfloat16_as_ushort(hb0)
                                     | ((uint32_t)__bfloat16_as_ushort(hb1) << 16);
                    hloN[mt][rr][nt] = (uint32_t)__bfloat16_as_ushort(__float2bfloat16(l0))
                                     | ((uint32_t)__bfloat16_as_ushort(__float2bfloat16(l1)) << 16);
                }
            }
        __syncthreads();   // all reads of SH/SX/sRed done

        // store new h images
        #pragma unroll
        for (int mt = 0; mt < 2; mt++)
            #pragma unroll
            for (int rr = 0; rr < 2; rr++) {
                int row = mt * 16 + rr * 8 + g;
                #pragma unroll
                for (int nt = 0; nt < 2; nt++) {
                    int cb = (colb0 + nt * 8) * 2;
                    *(uint32_t*)(smemS + SH_HI + row * 272 + cb) = hhiN[mt][rr][nt];
                    *(uint32_t*)(smemS + SH_LO + row * 272 + cb) = hloN[mt][rr][nt];
                }
            }
        // store feats image for t+1
        if (t < T_ - 1) {
            int r = tid >> 3, k0 = (tid & 7) * 8;
            float fs[8] = {fA.x, fA.y, fA.z, fA.w, fB.x, fB.y, fB.z, fB.w};
            #pragma unroll
            for (int j = 0; j < 4; j++) {
                __nv_bfloat162 hh = __floats2bfloat162_rn(fs[2 * j], fs[2 * j + 1]);
                float l0 = fs[2 * j]     - __bfloat162float(__low2bfloat16(hh));
                float l1 = fs[2 * j + 1] - __bfloat162float(__high2bfloat16(hh));
                __nv_bfloat162 ll = __floats2bfloat162_rn(l0, l1);
                int boff = r * 144 + k0 * 2 + j * 4;
                *(uint32_t*)(smemS + SX_HI + boff) = *(uint32_t*)&hh;
                *(uint32_t*)(smemS + SX_LO + boff) = *(uint32_t*)&ll;
            }
        }
        // y partials
        #pragma unroll
        for (int i = 0; i < 4; i++) {
            pacc[i] += __shfl_xor_sync(0xffffffffu, pacc[i], 1);
            pacc[i] += __shfl_xor_sync(0xffffffffu, pacc[i], 2);
        }
        if (tg == 0) {
            float b_add = (w == 0) ? bo_v : 0.f;
            sRf[w * 32 + g]      = pacc[0] + b_add;
            sRf[w * 32 + g + 8]  = pacc[1] + b_add;
            sRf[w * 32 + g + 16] = pacc[2] + b_add;
            sRf[w * 32 + g + 24] = pacc[3] + b_add;
        }
        __syncthreads();
    }

    // flush final step's y
    if (w == 0 && tg == 0) {
        #pragma unroll
        for (int q = 0; q < 4; q++) {
            int row = q * 8 + g;
            float y = sRf[row] + sRf[32 + row] + sRf[64 + row] + sRf[96 + row]
                    + sRf[128 + row] + sRf[160 + row] + sRf[192 + row] + sRf[224 + row];
            out[(size_t)(b0 + row) * T_ + (T_ - 1)] = y;
        }
    }
}

// ---------------------------------------------------------------------------
extern "C" void kernel_launch(void* const* d_in, const int* in_sizes, int n_in,
                              void* d_out, int out_size)
{
    const float* feats = (const float*)d_in[0];
    const float* h0    = (const float*)d_in[1];
    const float* y0    = (const float*)d_in[2];
    const float* W_ih  = (const float*)d_in[3];
    const float* W_hh  = (const float*)d_in[4];
    const float* b_ih  = (const float*)d_in[5];
    const float* b_hh  = (const float*)d_in[6];
    const float* Wo    = (const float*)d_in[7];
    const float* bo    = (const float*)d_in[8];
    float* out = (float*)d_out;

    cudaFuncSetAttribute(fused_kernel, cudaFuncAttributeMaxDynamicSharedMemorySize, S_TOT);
    fused_kernel<<<B_ / 32, 256, S_TOT>>>(feats, h0, y0, W_ih, W_hh, b_ih, b_hh,
                                          Wo, bo, out);
}